// round 2
// baseline (speedup 1.0000x reference)
#include <cuda_runtime.h>
#include <cstddef>

// Problem constants
constexpr int Tt   = 512;
constexpr int Bb   = 16;
constexpr int F    = 1024;   // FEAT
constexpr int INP  = 2048;
constexpr int OUTD = 1024;

// Persistent recurrence config
constexpr int NBLK = 128;    // 64 blocks per direction; all co-resident (<=148 SMs)
constexpr int PT   = 256;    // threads per persistent block
// dyn smem: hs[1024][16] + red[4][64][16] + fin[48][16]
constexpr int SM_HS  = F * Bb;          // 16384 floats
constexpr int SM_RED = 4 * 64 * Bb;     // 4096 floats
constexpr int SM_FIN = 48 * Bb;         // 768 floats
constexpr int STEP_SMEM = (SM_HS + SM_RED + SM_FIN) * (int)sizeof(float); // 84992 B

// ---------------------------------------------------------------------------
// Scratch (device global; no runtime allocation allowed)
// ---------------------------------------------------------------------------
constexpr size_t OFF_X    = 0;
constexpr size_t SZ_X     = (size_t)Tt * Bb * INP;
constexpr size_t OFF_H0   = OFF_X + SZ_X;
constexpr size_t SZ_H0    = (size_t)Tt * Bb * F;
constexpr size_t OFF_GX0  = OFF_H0 + SZ_H0;
constexpr size_t SZ_GX    = (size_t)2 * Tt * Bb * 3 * F;
constexpr size_t OFF_Y0   = OFF_GX0 + SZ_GX;
constexpr size_t SZ_Y     = (size_t)Tt * Bb * 2 * F;
constexpr size_t OFF_GX1  = OFF_Y0 + SZ_Y;
constexpr size_t OFF_Y1   = OFF_GX1 + SZ_GX;
constexpr size_t OFF_OUTT = OFF_Y1 + SZ_Y;
constexpr size_t SZ_OUTT  = (size_t)Tt * Bb * OUTD;
constexpr size_t OFF_WT0  = OFF_OUTT + SZ_OUTT;
constexpr size_t SZ_WT    = (size_t)2 * F * 3 * F;     // [2][1024][3072]
constexpr size_t OFF_WT1  = OFF_WT0 + SZ_WT;
constexpr size_t OFF_HG   = OFF_WT1 + SZ_WT;           // [2 parity][2 dir][1024][16]
constexpr size_t SZ_HG    = (size_t)2 * 2 * F * Bb;
constexpr size_t OFF_BAR  = OFF_HG + SZ_HG;            // barrier counter (as float bits)
constexpr size_t SZ_BAR   = 16;
constexpr size_t SCRATCH_TOTAL = OFF_BAR + SZ_BAR;

__device__ float g_scratch[SCRATCH_TOTAL];

// ---------------------------------------------------------------------------
// Transpose: inp [B][INP][T] -> X [T][B][INP]
// ---------------------------------------------------------------------------
__global__ void transpose_in_kernel(const float* __restrict__ in, float* __restrict__ out) {
    __shared__ float tile[32][33];
    int b  = blockIdx.z;
    int t0 = blockIdx.x * 32;
    int i0 = blockIdx.y * 32;
    int tx = threadIdx.x, ty = threadIdx.y;
#pragma unroll
    for (int j = 0; j < 32; j += 8)
        tile[ty + j][tx] = in[((size_t)b * INP + (i0 + ty + j)) * Tt + t0 + tx];
    __syncthreads();
#pragma unroll
    for (int j = 0; j < 32; j += 8)
        out[((size_t)(t0 + ty + j) * Bb + b) * INP + i0 + tx] = tile[tx][ty + j];
}

// ---------------------------------------------------------------------------
// Transpose: OUTT [(t*B+b)][o] -> out [B][OUT][T]
// ---------------------------------------------------------------------------
__global__ void transpose_out_kernel(const float* __restrict__ in, float* __restrict__ out) {
    __shared__ float tile[32][33];
    int b  = blockIdx.z;
    int t0 = blockIdx.x * 32;
    int o0 = blockIdx.y * 32;
    int tx = threadIdx.x, ty = threadIdx.y;
#pragma unroll
    for (int j = 0; j < 32; j += 8)
        tile[ty + j][tx] = in[((size_t)(t0 + ty + j) * Bb + b) * OUTD + o0 + tx];
    __syncthreads();
#pragma unroll
    for (int j = 0; j < 32; j += 8)
        out[((size_t)b * OUTD + (o0 + ty + j)) * Tt + t0 + tx] = tile[tx][ty + j];
}

// ---------------------------------------------------------------------------
// Transpose: whh [dir][3F][F] -> WT [dir][F][3F]
// ---------------------------------------------------------------------------
__global__ void transpose_w_kernel(const float* __restrict__ in, float* __restrict__ out) {
    __shared__ float tile[32][33];
    int d  = blockIdx.z;
    int r0 = blockIdx.x * 32;
    int k0 = blockIdx.y * 32;
    int tx = threadIdx.x, ty = threadIdx.y;
    const int R = 3 * F, K = F;
#pragma unroll
    for (int j = 0; j < 32; j += 8)
        tile[ty + j][tx] = in[(size_t)d * R * K + (size_t)(r0 + ty + j) * K + k0 + tx];
    __syncthreads();
#pragma unroll
    for (int j = 0; j < 32; j += 8)
        out[(size_t)d * K * R + (size_t)(k0 + ty + j) * R + r0 + tx] = tile[tx][ty + j];
}

// ---------------------------------------------------------------------------
// Generic GEMM: C[M,N] = A[M,K] * W[N,K]^T + bias[N]
// 128x128 tile, BK=16, 256 threads, 8x8 register tile.
// ---------------------------------------------------------------------------
__global__ void __launch_bounds__(256) gemm_nt_kernel(
    const float* __restrict__ A, const float* __restrict__ W,
    const float* __restrict__ bias, float* __restrict__ C,
    int M, int N, int K)
{
    __shared__ __align__(16) float As[16][128];
    __shared__ __align__(16) float Bs[16][128];

    int tid = threadIdx.x;
    int tx = tid & 15;
    int ty = tid >> 4;
    int bm = blockIdx.y * 128;
    int bn = blockIdx.x * 128;

    float acc[8][8];
#pragma unroll
    for (int i = 0; i < 8; ++i)
#pragma unroll
        for (int j = 0; j < 8; ++j) acc[i][j] = 0.f;

    int lr  = tid >> 1;
    int lc0 = (tid & 1) * 8;

    const float* Ag = A + (size_t)(bm + lr) * K;
    const float* Wg = W + (size_t)(bn + lr) * K;

    for (int k0 = 0; k0 < K; k0 += 16) {
        float4 av0 = *(const float4*)(Ag + k0 + lc0);
        float4 av1 = *(const float4*)(Ag + k0 + lc0 + 4);
        float4 bv0 = *(const float4*)(Wg + k0 + lc0);
        float4 bv1 = *(const float4*)(Wg + k0 + lc0 + 4);

        As[lc0 + 0][lr] = av0.x; As[lc0 + 1][lr] = av0.y;
        As[lc0 + 2][lr] = av0.z; As[lc0 + 3][lr] = av0.w;
        As[lc0 + 4][lr] = av1.x; As[lc0 + 5][lr] = av1.y;
        As[lc0 + 6][lr] = av1.z; As[lc0 + 7][lr] = av1.w;

        Bs[lc0 + 0][lr] = bv0.x; Bs[lc0 + 1][lr] = bv0.y;
        Bs[lc0 + 2][lr] = bv0.z; Bs[lc0 + 3][lr] = bv0.w;
        Bs[lc0 + 4][lr] = bv1.x; Bs[lc0 + 5][lr] = bv1.y;
        Bs[lc0 + 6][lr] = bv1.z; Bs[lc0 + 7][lr] = bv1.w;

        __syncthreads();

#pragma unroll
        for (int kk = 0; kk < 16; ++kk) {
            float4 a0 = *(const float4*)&As[kk][ty * 8];
            float4 a1 = *(const float4*)&As[kk][ty * 8 + 4];
            float4 b0 = *(const float4*)&Bs[kk][tx * 8];
            float4 b1 = *(const float4*)&Bs[kk][tx * 8 + 4];
            float am[8]  = {a0.x, a0.y, a0.z, a0.w, a1.x, a1.y, a1.z, a1.w};
            float bn_[8] = {b0.x, b0.y, b0.z, b0.w, b1.x, b1.y, b1.z, b1.w};
#pragma unroll
            for (int i = 0; i < 8; ++i)
#pragma unroll
                for (int j = 0; j < 8; ++j)
                    acc[i][j] += am[i] * bn_[j];
        }
        __syncthreads();
    }

    float bv[8];
#pragma unroll
    for (int j = 0; j < 8; ++j) bv[j] = bias[bn + tx * 8 + j];

#pragma unroll
    for (int i = 0; i < 8; ++i) {
        size_t base = (size_t)(bm + ty * 8 + i) * N + bn + tx * 8;
        float4 c0, c1;
        c0.x = acc[i][0] + bv[0]; c0.y = acc[i][1] + bv[1];
        c0.z = acc[i][2] + bv[2]; c0.w = acc[i][3] + bv[3];
        c1.x = acc[i][4] + bv[4]; c1.y = acc[i][5] + bv[5];
        c1.z = acc[i][6] + bv[6]; c1.w = acc[i][7] + bv[7];
        *(float4*)(C + base)     = c0;
        *(float4*)(C + base + 4) = c1;
    }
}

// ---------------------------------------------------------------------------
__global__ void zero_kernel(float* p, int n) {
    int i = blockIdx.x * blockDim.x + threadIdx.x;
    if (i < n) p[i] = 0.f;
}

// ---------------------------------------------------------------------------
// Persistent bidirectional GRU layer.
// grid = 128 blocks (64 per direction), 256 threads, one launch per layer.
// Per step: stage h^T[k][b] in smem, compute gh = WT^T h (k-split x4 per block),
// reduce, apply gates, write new h (double-buffered in global), grid barrier.
// ---------------------------------------------------------------------------
__device__ __forceinline__ unsigned ld_acquire(const unsigned* p) {
    unsigned v;
    asm volatile("ld.global.acquire.gpu.u32 %0, [%1];" : "=r"(v) : "l"(p) : "memory");
    return v;
}

__global__ void __launch_bounds__(PT, 1) gru_layer_kernel(
    const float* __restrict__ WT,    // [2][F][3F]  (k-major)
    const float* __restrict__ bhh,   // [2][3F]
    const float* __restrict__ gx,    // [2][Tt][Bb][3F]
    float* __restrict__ y,           // [Tt][Bb][2][F]
    float* __restrict__ hG,          // [2 parity][2 dir][F][Bb]
    unsigned* __restrict__ bar)
{
    extern __shared__ float sm[];
    float* hs  = sm;                 // [F][Bb]  (h^T)
    float* red = sm + SM_HS;         // [4][64][Bb]
    float* fin = red + SM_RED;       // [48][Bb]

    const int tid = threadIdx.x;
    const int dir = blockIdx.x >> 6;
    const int u0  = (blockIdx.x & 63) * 16;
    const int c   = tid >> 6;        // k chunk 0..3
    const int gu  = tid & 63;        // (gate,unit) slot; 48 active
    const int g   = gu >> 4;
    const int u   = gu & 15;
    const bool active = gu < 48;
    const int row = g * F + u0 + u;

    const float* wbase = WT + (size_t)dir * F * 3 * F;
    const float* bb    = bhh + (size_t)dir * 3 * F;

    for (int s = 0; s < Tt; ++s) {
        const int cur = s & 1, nxt = cur ^ 1;
        const int tt  = dir ? (Tt - 1 - s) : s;

        // Stage h^T (current parity, own direction) into smem
        {
            const float4* src = (const float4*)(hG + ((size_t)(cur * 2 + dir)) * F * Bb);
            float4* dst = (float4*)hs;
#pragma unroll
            for (int i = tid; i < F * Bb / 4; i += PT) dst[i] = src[i];
        }
        __syncthreads();

        // Partial dot products over this thread's k chunk, 16 batches
        if (active) {
            float acc[16];
#pragma unroll
            for (int b = 0; b < 16; ++b) acc[b] = 0.f;

            const float*  wp = wbase + (size_t)(c * 256) * (3 * F) + row;
            const float4* hp = (const float4*)hs + (size_t)(c * 256) * 4;

#pragma unroll 4
            for (int kl = 0; kl < 256; ++kl) {
                float  w  = wp[(size_t)kl * (3 * F)];
                float4 h0 = hp[kl * 4 + 0];
                float4 h1 = hp[kl * 4 + 1];
                float4 h2 = hp[kl * 4 + 2];
                float4 h3 = hp[kl * 4 + 3];
                acc[0]  += w * h0.x; acc[1]  += w * h0.y; acc[2]  += w * h0.z; acc[3]  += w * h0.w;
                acc[4]  += w * h1.x; acc[5]  += w * h1.y; acc[6]  += w * h1.z; acc[7]  += w * h1.w;
                acc[8]  += w * h2.x; acc[9]  += w * h2.y; acc[10] += w * h2.z; acc[11] += w * h2.w;
                acc[12] += w * h3.x; acc[13] += w * h3.y; acc[14] += w * h3.z; acc[15] += w * h3.w;
            }
#pragma unroll
            for (int b = 0; b < 16; ++b) red[((size_t)c * 64 + gu) * Bb + b] = acc[b];
        }
        __syncthreads();

        // Reduce 4 k-chunk partials: 48*16 sums over 256 threads
        for (int p = tid; p < 48 * Bb; p += PT) {
            int rg = p >> 4, b = p & 15;
            fin[p] = red[(0 * 64 + rg) * Bb + b] + red[(1 * 64 + rg) * Bb + b]
                   + red[(2 * 64 + rg) * Bb + b] + red[(3 * 64 + rg) * Bb + b];
        }
        __syncthreads();

        // Gates + hidden update: thread = (unit u2, batch b)
        {
            int u2 = tid >> 4, b = tid & 15;
            int j  = u0 + u2;
            float ghr = fin[(0 * 16 + u2) * Bb + b] + bb[j];
            float ghz = fin[(1 * 16 + u2) * Bb + b] + bb[F + j];
            float ghn = fin[(2 * 16 + u2) * Bb + b] + bb[2 * F + j];

            const float* gxp = gx + (((size_t)dir * Tt + tt) * Bb + b) * (size_t)(3 * F);
            float xr = gxp[j];
            float xz = gxp[F + j];
            float xn = gxp[2 * F + j];

            float r = 1.f / (1.f + expf(-(xr + ghr)));
            float z = 1.f / (1.f + expf(-(xz + ghz)));
            float n = tanhf(xn + r * ghn);

            float hprev = hs[(size_t)j * Bb + b];
            float hnew  = (1.f - z) * n + z * hprev;

            hG[((size_t)(nxt * 2 + dir) * F + j) * Bb + b] = hnew;
            y[(((size_t)tt * Bb + b) * 2 + dir) * F + j]   = hnew;
        }

        // Grid barrier (monotone counter; counter zeroed before launch)
        __syncthreads();
        if (tid == 0) {
            __threadfence();
            atomicAdd(bar, 1u);
            unsigned tgt = (unsigned)(s + 1) * gridDim.x;
            while (ld_acquire(bar) < tgt) { }
            __threadfence();
        }
        __syncthreads();
    }
}

// ---------------------------------------------------------------------------
extern "C" void kernel_launch(void* const* d_in, const int* in_sizes, int n_in,
                              void* d_out, int out_size)
{
    const float* inp     = (const float*)d_in[0];
    const float* w_in    = (const float*)d_in[1];
    const float* b_in    = (const float*)d_in[2];
    const float* w_ih_l0 = (const float*)d_in[3];
    const float* w_hh_l0 = (const float*)d_in[4];
    const float* b_ih_l0 = (const float*)d_in[5];
    const float* b_hh_l0 = (const float*)d_in[6];
    const float* w_ih_l1 = (const float*)d_in[7];
    const float* w_hh_l1 = (const float*)d_in[8];
    const float* b_ih_l1 = (const float*)d_in[9];
    const float* b_hh_l1 = (const float*)d_in[10];
    const float* w_out   = (const float*)d_in[11];
    const float* b_out   = (const float*)d_in[12];
    float* out = (float*)d_out;

    float* S = nullptr;
    cudaGetSymbolAddress((void**)&S, g_scratch);

    float* X    = S + OFF_X;
    float* H0   = S + OFF_H0;
    float* GX0  = S + OFF_GX0;
    float* Y0   = S + OFF_Y0;
    float* GX1  = S + OFF_GX1;
    float* Y1   = S + OFF_Y1;
    float* OUTT = S + OFF_OUTT;
    float* WT0  = S + OFF_WT0;
    float* WT1  = S + OFF_WT1;
    float* HG   = S + OFF_HG;
    unsigned* BAR = (unsigned*)(S + OFF_BAR);

    cudaFuncSetAttribute(gru_layer_kernel,
                         cudaFuncAttributeMaxDynamicSharedMemorySize, STEP_SMEM);

    const int M = Tt * Bb;  // 8192

    // 1) Transpose input
    transpose_in_kernel<<<dim3(Tt / 32, INP / 32, Bb), dim3(32, 8)>>>(inp, X);

    // 2) Input projection
    gemm_nt_kernel<<<dim3(F / 128, M / 128), 256>>>(X, w_in, b_in, H0, M, F, INP);

    // 3) Layer 0: W_hh transpose + input-gate preactivations
    transpose_w_kernel<<<dim3(3 * F / 32, F / 32, 2), dim3(32, 8)>>>(w_hh_l0, WT0);
    for (int d = 0; d < 2; ++d) {
        gemm_nt_kernel<<<dim3(3 * F / 128, M / 128), 256>>>(
            H0, w_ih_l0 + (size_t)d * 3 * F * F, b_ih_l0 + (size_t)d * 3 * F,
            GX0 + (size_t)d * Tt * Bb * 3 * F, M, 3 * F, F);
    }

    // 4) Layer 0 recurrence (persistent, 1 launch)
    zero_kernel<<<(int)((SZ_HG + SZ_BAR + 255) / 256), 256>>>(HG, (int)(SZ_HG + SZ_BAR));
    gru_layer_kernel<<<NBLK, PT, STEP_SMEM>>>(WT0, b_hh_l0, GX0, Y0, HG, BAR);

    // 5) Layer 1: W_hh transpose + input-gate preactivations
    transpose_w_kernel<<<dim3(3 * F / 32, F / 32, 2), dim3(32, 8)>>>(w_hh_l1, WT1);
    for (int d = 0; d < 2; ++d) {
        gemm_nt_kernel<<<dim3(3 * F / 128, M / 128), 256>>>(
            Y0, w_ih_l1 + (size_t)d * 3 * F * 2 * F, b_ih_l1 + (size_t)d * 3 * F,
            GX1 + (size_t)d * Tt * Bb * 3 * F, M, 3 * F, 2 * F);
    }

    // 6) Layer 1 recurrence
    zero_kernel<<<(int)((SZ_HG + SZ_BAR + 255) / 256), 256>>>(HG, (int)(SZ_HG + SZ_BAR));
    gru_layer_kernel<<<NBLK, PT, STEP_SMEM>>>(WT1, b_hh_l1, GX1, Y1, HG, BAR);

    // 7) Output projection
    gemm_nt_kernel<<<dim3(OUTD / 128, M / 128), 256>>>(Y1, w_out, b_out, OUTT, M, OUTD, 2 * F);

    // 8) Final transpose to [B, OUT, T]
    transpose_out_kernel<<<dim3(Tt / 32, OUTD / 32, Bb), dim3(32, 8)>>>(OUTT, out);
}

// round 3
// speedup vs baseline: 1.2345x; 1.2345x over previous
#include <cuda_runtime.h>
#include <cuda_bf16.h>
#include <cstddef>

// Problem constants
constexpr int Tt   = 512;
constexpr int Bb   = 16;
constexpr int F    = 1024;   // FEAT
constexpr int INP  = 2048;
constexpr int OUTD = 1024;

// Persistent recurrence config
constexpr int NBLK = 128;
constexpr int PT   = 256;
constexpr int SM_HS  = F * Bb;
constexpr int SM_RED = 4 * 64 * Bb;
constexpr int SM_FIN = 48 * Bb;
constexpr int STEP_SMEM = (SM_HS + SM_RED + SM_FIN) * (int)sizeof(float);

// ---------------------------------------------------------------------------
// Float scratch
// ---------------------------------------------------------------------------
constexpr size_t OFF_X    = 0;
constexpr size_t SZ_X     = (size_t)Tt * Bb * INP;
constexpr size_t OFF_H0   = OFF_X + SZ_X;
constexpr size_t SZ_H0    = (size_t)Tt * Bb * F;
constexpr size_t OFF_GX0  = OFF_H0 + SZ_H0;
constexpr size_t SZ_GX    = (size_t)Tt * Bb * 6 * F;   // [M][6144]
constexpr size_t OFF_Y0   = OFF_GX0 + SZ_GX;
constexpr size_t SZ_Y     = (size_t)Tt * Bb * 2 * F;
constexpr size_t OFF_GX1  = OFF_Y0 + SZ_Y;
constexpr size_t OFF_Y1   = OFF_GX1 + SZ_GX;
constexpr size_t OFF_OUTT = OFF_Y1 + SZ_Y;
constexpr size_t SZ_OUTT  = (size_t)Tt * Bb * OUTD;
constexpr size_t OFF_WT0  = OFF_OUTT + SZ_OUTT;
constexpr size_t SZ_WT    = (size_t)2 * F * 3 * F;
constexpr size_t OFF_WT1  = OFF_WT0 + SZ_WT;
constexpr size_t OFF_HG   = OFF_WT1 + SZ_WT;
constexpr size_t SZ_HG    = (size_t)2 * 2 * F * Bb;
constexpr size_t OFF_BAR  = OFF_HG + SZ_HG;
constexpr size_t SZ_BAR   = 16;
constexpr size_t SCRATCH_TOTAL = OFF_BAR + SZ_BAR;

__device__ float g_scratch[SCRATCH_TOTAL];

// ---------------------------------------------------------------------------
// bf16 scratch (hi/lo split planes)
// ---------------------------------------------------------------------------
constexpr size_t SZ_Xe   = (size_t)Tt * Bb * INP;        // 16.8M
constexpr size_t SZ_H0e  = (size_t)Tt * Bb * F;          // 8.4M
constexpr size_t SZ_Ye   = (size_t)Tt * Bb * 2 * F;      // 16.8M
constexpr size_t SZ_WINe = (size_t)F * INP;              // 2.1M
constexpr size_t SZ_WI0e = (size_t)6 * F * F;            // 6.3M
constexpr size_t SZ_WI1e = (size_t)6 * F * 2 * F;        // 12.6M
constexpr size_t SZ_WOe  = (size_t)OUTD * 2 * F;         // 2.1M

constexpr size_t BOFF_XH  = 0;
constexpr size_t BOFF_XL  = BOFF_XH  + SZ_Xe;
constexpr size_t BOFF_H0H = BOFF_XL  + SZ_Xe;
constexpr size_t BOFF_H0L = BOFF_H0H + SZ_H0e;
constexpr size_t BOFF_Y0H = BOFF_H0L + SZ_H0e;
constexpr size_t BOFF_Y0L = BOFF_Y0H + SZ_Ye;
constexpr size_t BOFF_Y1H = BOFF_Y0L + SZ_Ye;
constexpr size_t BOFF_Y1L = BOFF_Y1H + SZ_Ye;
constexpr size_t BOFF_WINH= BOFF_Y1L + SZ_Ye;
constexpr size_t BOFF_WINL= BOFF_WINH+ SZ_WINe;
constexpr size_t BOFF_WI0H= BOFF_WINL+ SZ_WINe;
constexpr size_t BOFF_WI0L= BOFF_WI0H+ SZ_WI0e;
constexpr size_t BOFF_WI1H= BOFF_WI0L+ SZ_WI0e;
constexpr size_t BOFF_WI1L= BOFF_WI1H+ SZ_WI1e;
constexpr size_t BOFF_WOH = BOFF_WI1L+ SZ_WI1e;
constexpr size_t BOFF_WOL = BOFF_WOH + SZ_WOe;
constexpr size_t BF_TOTAL = BOFF_WOL + SZ_WOe;

__device__ __nv_bfloat16 g_bf[BF_TOTAL];

// ---------------------------------------------------------------------------
// Elementwise split: x -> (hi, lo) bf16
// ---------------------------------------------------------------------------
__global__ void split_kernel(const float* __restrict__ x,
                             __nv_bfloat16* __restrict__ h,
                             __nv_bfloat16* __restrict__ l, int n)
{
    int i = blockIdx.x * blockDim.x + threadIdx.x;
    if (i < n) {
        float v = x[i];
        __nv_bfloat16 hi = __float2bfloat16(v);
        float r = v - __bfloat162float(hi);
        h[i] = hi;
        l[i] = __float2bfloat16(r);
    }
}

// ---------------------------------------------------------------------------
// Transposes
// ---------------------------------------------------------------------------
__global__ void transpose_in_kernel(const float* __restrict__ in, float* __restrict__ out) {
    __shared__ float tile[32][33];
    int b  = blockIdx.z;
    int t0 = blockIdx.x * 32;
    int i0 = blockIdx.y * 32;
    int tx = threadIdx.x, ty = threadIdx.y;
#pragma unroll
    for (int j = 0; j < 32; j += 8)
        tile[ty + j][tx] = in[((size_t)b * INP + (i0 + ty + j)) * Tt + t0 + tx];
    __syncthreads();
#pragma unroll
    for (int j = 0; j < 32; j += 8)
        out[((size_t)(t0 + ty + j) * Bb + b) * INP + i0 + tx] = tile[tx][ty + j];
}

__global__ void transpose_out_kernel(const float* __restrict__ in, float* __restrict__ out) {
    __shared__ float tile[32][33];
    int b  = blockIdx.z;
    int t0 = blockIdx.x * 32;
    int o0 = blockIdx.y * 32;
    int tx = threadIdx.x, ty = threadIdx.y;
#pragma unroll
    for (int j = 0; j < 32; j += 8)
        tile[ty + j][tx] = in[((size_t)(t0 + ty + j) * Bb + b) * OUTD + o0 + tx];
    __syncthreads();
#pragma unroll
    for (int j = 0; j < 32; j += 8)
        out[((size_t)b * OUTD + (o0 + ty + j)) * Tt + t0 + tx] = tile[tx][ty + j];
}

__global__ void transpose_w_kernel(const float* __restrict__ in, float* __restrict__ out) {
    __shared__ float tile[32][33];
    int d  = blockIdx.z;
    int r0 = blockIdx.x * 32;
    int k0 = blockIdx.y * 32;
    int tx = threadIdx.x, ty = threadIdx.y;
    const int R = 3 * F, K = F;
#pragma unroll
    for (int j = 0; j < 32; j += 8)
        tile[ty + j][tx] = in[(size_t)d * R * K + (size_t)(r0 + ty + j) * K + k0 + tx];
    __syncthreads();
#pragma unroll
    for (int j = 0; j < 32; j += 8)
        out[(size_t)d * K * R + (size_t)(k0 + ty + j) * R + r0 + tx] = tile[tx][ty + j];
}

// ---------------------------------------------------------------------------
// Tensor-core split-bf16 GEMM: C[M,N] = A[M,K] * W[N,K]^T + bias
// A,W given as (hi,lo) bf16 planes; fp32 accumulate of hi*hi + hi*lo + lo*hi.
// 128x128 tile, BK=32, 256 thr = 8 warps in 2(m) x 4(n), warp tile 64x32.
// cp.async double-buffered staging. Smem row stride 56 bf16 (conflict-free).
// ---------------------------------------------------------------------------
constexpr int TW  = 56;            // bf16 per smem row
constexpr int PL  = 128 * TW;      // plane size (bf16)
constexpr int GBUF = 4 * PL;       // 4 planes per buffer
constexpr int SMEM_GEMM = 2 * GBUF * (int)sizeof(__nv_bfloat16);  // 114688

__device__ __forceinline__ void cpa16(void* sdst, const void* gsrc) {
    unsigned s = (unsigned)__cvta_generic_to_shared(sdst);
    asm volatile("cp.async.cg.shared.global [%0], [%1], 16;\n" :: "r"(s), "l"(gsrc));
}
__device__ __forceinline__ void cpa_commit() {
    asm volatile("cp.async.commit_group;\n" ::);
}
__device__ __forceinline__ void cpa_wait0() {
    asm volatile("cp.async.wait_group 0;\n" ::);
}
__device__ __forceinline__ void mma_bf16(float* c, const unsigned* a, const unsigned* b) {
    asm volatile(
        "mma.sync.aligned.m16n8k16.row.col.f32.bf16.bf16.f32 "
        "{%0,%1,%2,%3},{%4,%5,%6,%7},{%8,%9},{%0,%1,%2,%3};\n"
        : "+f"(c[0]), "+f"(c[1]), "+f"(c[2]), "+f"(c[3])
        : "r"(a[0]), "r"(a[1]), "r"(a[2]), "r"(a[3]), "r"(b[0]), "r"(b[1]));
}

__global__ void __launch_bounds__(256) gemm_bf16_split_kernel(
    const __nv_bfloat16* __restrict__ Ah, const __nv_bfloat16* __restrict__ Al,
    const __nv_bfloat16* __restrict__ Wh, const __nv_bfloat16* __restrict__ Wl,
    const float* __restrict__ bias, float* __restrict__ C,
    int M, int N, int K)
{
    extern __shared__ __nv_bfloat16 smx[];
    const int tid = threadIdx.x;
    const int bm = blockIdx.y * 128, bn = blockIdx.x * 128;
    const int lane = tid & 31, wid = tid >> 5;
    const int wm = wid & 1, wn = wid >> 1;
    const int g = lane >> 2, t = lane & 3;

    float acc[4][4][4];
#pragma unroll
    for (int i = 0; i < 4; ++i)
#pragma unroll
        for (int j = 0; j < 4; ++j)
#pragma unroll
            for (int q = 0; q < 4; ++q) acc[i][j][q] = 0.f;

    const int r0 = tid >> 2;            // staging row (chunk 0)
    const int c0 = (tid & 3) * 8;       // staging bf16 col
    const int nk = K / 32;

    // --- prologue stage ---
    {
        __nv_bfloat16* s = smx;
#pragma unroll
        for (int p = 0; p < 2; ++p) {
            int row = r0 + p * 64;
            size_t ga = (size_t)(bm + row) * K + c0;
            size_t gw = (size_t)(bn + row) * K + c0;
            int so = row * TW + c0;
            cpa16(s + 0 * PL + so, Ah + ga);
            cpa16(s + 1 * PL + so, Al + ga);
            cpa16(s + 2 * PL + so, Wh + gw);
            cpa16(s + 3 * PL + so, Wl + gw);
        }
        cpa_commit();
    }

    for (int kt = 0; kt < nk; ++kt) {
        cpa_wait0();
        __syncthreads();

        if (kt + 1 < nk) {
            __nv_bfloat16* s = smx + ((kt + 1) & 1) * GBUF;
            int k0 = (kt + 1) * 32;
#pragma unroll
            for (int p = 0; p < 2; ++p) {
                int row = r0 + p * 64;
                size_t ga = (size_t)(bm + row) * K + k0 + c0;
                size_t gw = (size_t)(bn + row) * K + k0 + c0;
                int so = row * TW + c0;
                cpa16(s + 0 * PL + so, Ah + ga);
                cpa16(s + 1 * PL + so, Al + ga);
                cpa16(s + 2 * PL + so, Wh + gw);
                cpa16(s + 3 * PL + so, Wl + gw);
            }
            cpa_commit();
        }

        const __nv_bfloat16* sb = smx + (kt & 1) * GBUF;
        const unsigned* pAh = (const unsigned*)(sb + 0 * PL);
        const unsigned* pAl = (const unsigned*)(sb + 1 * PL);
        const unsigned* pWh = (const unsigned*)(sb + 2 * PL);
        const unsigned* pWl = (const unsigned*)(sb + 3 * PL);

#pragma unroll
        for (int ks = 0; ks < 2; ++ks) {
            unsigned aH[4][4], aL[4][4], bH[4][2], bL[4][2];
#pragma unroll
            for (int i = 0; i < 4; ++i) {
                int rb = (wm * 64 + i * 16 + g) * 28 + ks * 8 + t;
                aH[i][0] = pAh[rb];           aH[i][2] = pAh[rb + 4];
                aH[i][1] = pAh[rb + 8 * 28];  aH[i][3] = pAh[rb + 8 * 28 + 4];
                aL[i][0] = pAl[rb];           aL[i][2] = pAl[rb + 4];
                aL[i][1] = pAl[rb + 8 * 28];  aL[i][3] = pAl[rb + 8 * 28 + 4];
            }
#pragma unroll
            for (int j = 0; j < 4; ++j) {
                int rb = (wn * 32 + j * 8 + g) * 28 + ks * 8 + t;
                bH[j][0] = pWh[rb]; bH[j][1] = pWh[rb + 4];
                bL[j][0] = pWl[rb]; bL[j][1] = pWl[rb + 4];
            }
#pragma unroll
            for (int i = 0; i < 4; ++i)
#pragma unroll
                for (int j = 0; j < 4; ++j) {
                    mma_bf16(acc[i][j], aH[i], bH[j]);
                    mma_bf16(acc[i][j], aH[i], bL[j]);
                    mma_bf16(acc[i][j], aL[i], bH[j]);
                }
        }
    }

    // Epilogue: bias + store fp32
#pragma unroll
    for (int i = 0; i < 4; ++i) {
        int row0 = bm + wm * 64 + i * 16 + g;
#pragma unroll
        for (int j = 0; j < 4; ++j) {
            int col = bn + wn * 32 + j * 8 + t * 2;
            float b0 = bias[col], b1 = bias[col + 1];
            float2 v0 = make_float2(acc[i][j][0] + b0, acc[i][j][1] + b1);
            float2 v1 = make_float2(acc[i][j][2] + b0, acc[i][j][3] + b1);
            *(float2*)(C + (size_t)row0 * N + col) = v0;
            *(float2*)(C + (size_t)(row0 + 8) * N + col) = v1;
        }
    }
}

// ---------------------------------------------------------------------------
__global__ void zero_kernel(float* p, int n) {
    int i = blockIdx.x * blockDim.x + threadIdx.x;
    if (i < n) p[i] = 0.f;
}

// ---------------------------------------------------------------------------
// Persistent bidirectional GRU layer (unchanged except gx layout [M][6144])
// ---------------------------------------------------------------------------
__device__ __forceinline__ unsigned ld_acquire(const unsigned* p) {
    unsigned v;
    asm volatile("ld.global.acquire.gpu.u32 %0, [%1];" : "=r"(v) : "l"(p) : "memory");
    return v;
}

__global__ void __launch_bounds__(PT, 1) gru_layer_kernel(
    const float* __restrict__ WT,    // [2][F][3F]
    const float* __restrict__ bhh,   // [2][3F]
    const float* __restrict__ gx,    // [Tt*Bb][6F]  (dir halves)
    float* __restrict__ y,           // [Tt][Bb][2][F]
    float* __restrict__ hG,          // [2 parity][2 dir][F][Bb]
    unsigned* __restrict__ bar)
{
    extern __shared__ float sm[];
    float* hs  = sm;
    float* red = sm + SM_HS;
    float* fin = red + SM_RED;

    const int tid = threadIdx.x;
    const int dir = blockIdx.x >> 6;
    const int u0  = (blockIdx.x & 63) * 16;
    const int c   = tid >> 6;
    const int gu  = tid & 63;
    const int g   = gu >> 4;
    const int u   = gu & 15;
    const bool active = gu < 48;
    const int row = g * F + u0 + u;

    const float* wbase = WT + (size_t)dir * F * 3 * F;
    const float* bb    = bhh + (size_t)dir * 3 * F;

    for (int s = 0; s < Tt; ++s) {
        const int cur = s & 1, nxt = cur ^ 1;
        const int tt  = dir ? (Tt - 1 - s) : s;

        {
            const float4* src = (const float4*)(hG + ((size_t)(cur * 2 + dir)) * F * Bb);
            float4* dst = (float4*)hs;
#pragma unroll
            for (int i = tid; i < F * Bb / 4; i += PT) dst[i] = src[i];
        }
        __syncthreads();

        if (active) {
            float acc[16];
#pragma unroll
            for (int b = 0; b < 16; ++b) acc[b] = 0.f;

            const float*  wp = wbase + (size_t)(c * 256) * (3 * F) + row;
            const float4* hp = (const float4*)hs + (size_t)(c * 256) * 4;

#pragma unroll 4
            for (int kl = 0; kl < 256; ++kl) {
                float  w  = wp[(size_t)kl * (3 * F)];
                float4 h0 = hp[kl * 4 + 0];
                float4 h1 = hp[kl * 4 + 1];
                float4 h2 = hp[kl * 4 + 2];
                float4 h3 = hp[kl * 4 + 3];
                acc[0]  += w * h0.x; acc[1]  += w * h0.y; acc[2]  += w * h0.z; acc[3]  += w * h0.w;
                acc[4]  += w * h1.x; acc[5]  += w * h1.y; acc[6]  += w * h1.z; acc[7]  += w * h1.w;
                acc[8]  += w * h2.x; acc[9]  += w * h2.y; acc[10] += w * h2.z; acc[11] += w * h2.w;
                acc[12] += w * h3.x; acc[13] += w * h3.y; acc[14] += w * h3.z; acc[15] += w * h3.w;
            }
#pragma unroll
            for (int b = 0; b < 16; ++b) red[((size_t)c * 64 + gu) * Bb + b] = acc[b];
        }
        __syncthreads();

        for (int p = tid; p < 48 * Bb; p += PT) {
            int rg = p >> 4, b = p & 15;
            fin[p] = red[(0 * 64 + rg) * Bb + b] + red[(1 * 64 + rg) * Bb + b]
                   + red[(2 * 64 + rg) * Bb + b] + red[(3 * 64 + rg) * Bb + b];
        }
        __syncthreads();

        {
            int u2 = tid >> 4, b = tid & 15;
            int j  = u0 + u2;
            float ghr = fin[(0 * 16 + u2) * Bb + b] + bb[j];
            float ghz = fin[(1 * 16 + u2) * Bb + b] + bb[F + j];
            float ghn = fin[(2 * 16 + u2) * Bb + b] + bb[2 * F + j];

            const float* gxp = gx + ((size_t)tt * Bb + b) * (size_t)(6 * F) + (size_t)dir * 3 * F;
            float xr = gxp[j];
            float xz = gxp[F + j];
            float xn = gxp[2 * F + j];

            float r = 1.f / (1.f + expf(-(xr + ghr)));
            float z = 1.f / (1.f + expf(-(xz + ghz)));
            float n = tanhf(xn + r * ghn);

            float hprev = hs[(size_t)j * Bb + b];
            float hnew  = (1.f - z) * n + z * hprev;

            hG[((size_t)(nxt * 2 + dir) * F + j) * Bb + b] = hnew;
            y[(((size_t)tt * Bb + b) * 2 + dir) * F + j]   = hnew;
        }

        __syncthreads();
        if (tid == 0) {
            __threadfence();
            atomicAdd(bar, 1u);
            unsigned tgt = (unsigned)(s + 1) * gridDim.x;
            while (ld_acquire(bar) < tgt) { }
            __threadfence();
        }
        __syncthreads();
    }
}

// ---------------------------------------------------------------------------
extern "C" void kernel_launch(void* const* d_in, const int* in_sizes, int n_in,
                              void* d_out, int out_size)
{
    const float* inp     = (const float*)d_in[0];
    const float* w_in    = (const float*)d_in[1];
    const float* b_in    = (const float*)d_in[2];
    const float* w_ih_l0 = (const float*)d_in[3];
    const float* w_hh_l0 = (const float*)d_in[4];
    const float* b_ih_l0 = (const float*)d_in[5];
    const float* b_hh_l0 = (const float*)d_in[6];
    const float* w_ih_l1 = (const float*)d_in[7];
    const float* w_hh_l1 = (const float*)d_in[8];
    const float* b_ih_l1 = (const float*)d_in[9];
    const float* b_hh_l1 = (const float*)d_in[10];
    const float* w_out   = (const float*)d_in[11];
    const float* b_out   = (const float*)d_in[12];
    float* out = (float*)d_out;

    float* S = nullptr;
    cudaGetSymbolAddress((void**)&S, g_scratch);
    __nv_bfloat16* BF = nullptr;
    cudaGetSymbolAddress((void**)&BF, g_bf);

    float* X    = S + OFF_X;
    float* H0   = S + OFF_H0;
    float* GX0  = S + OFF_GX0;
    float* Y0   = S + OFF_Y0;
    float* GX1  = S + OFF_GX1;
    float* Y1   = S + OFF_Y1;
    float* OUTT = S + OFF_OUTT;
    float* WT0  = S + OFF_WT0;
    float* WT1  = S + OFF_WT1;
    float* HG   = S + OFF_HG;
    unsigned* BAR = (unsigned*)(S + OFF_BAR);

    cudaFuncSetAttribute(gru_layer_kernel,
                         cudaFuncAttributeMaxDynamicSharedMemorySize, STEP_SMEM);
    cudaFuncSetAttribute(gemm_bf16_split_kernel,
                         cudaFuncAttributeMaxDynamicSharedMemorySize, SMEM_GEMM);

    const int M = Tt * Bb;  // 8192
    auto nb = [](size_t n) { return (int)((n + 255) / 256); };

    // 1) Transpose input + split
    transpose_in_kernel<<<dim3(Tt / 32, INP / 32, Bb), dim3(32, 8)>>>(inp, X);
    split_kernel<<<nb(SZ_Xe), 256>>>(X, BF + BOFF_XH, BF + BOFF_XL, (int)SZ_Xe);

    // Weight splits (all independent)
    split_kernel<<<nb(SZ_WINe), 256>>>(w_in,    BF + BOFF_WINH, BF + BOFF_WINL, (int)SZ_WINe);
    split_kernel<<<nb(SZ_WI0e), 256>>>(w_ih_l0, BF + BOFF_WI0H, BF + BOFF_WI0L, (int)SZ_WI0e);
    split_kernel<<<nb(SZ_WI1e), 256>>>(w_ih_l1, BF + BOFF_WI1H, BF + BOFF_WI1L, (int)SZ_WI1e);
    split_kernel<<<nb(SZ_WOe),  256>>>(w_out,   BF + BOFF_WOH,  BF + BOFF_WOL,  (int)SZ_WOe);

    // 2) Input projection: H0 = X * w_in^T + b_in   [8192,1024,K=2048]
    gemm_bf16_split_kernel<<<dim3(F / 128, M / 128), 256, SMEM_GEMM>>>(
        BF + BOFF_XH, BF + BOFF_XL, BF + BOFF_WINH, BF + BOFF_WINL, b_in, H0, M, F, INP);
    split_kernel<<<nb(SZ_H0e), 256>>>(H0, BF + BOFF_H0H, BF + BOFF_H0L, (int)SZ_H0e);

    // 3) Layer 0: gx for both dirs in one GEMM  [8192,6144,K=1024]
    transpose_w_kernel<<<dim3(3 * F / 32, F / 32, 2), dim3(32, 8)>>>(w_hh_l0, WT0);
    gemm_bf16_split_kernel<<<dim3(6 * F / 128, M / 128), 256, SMEM_GEMM>>>(
        BF + BOFF_H0H, BF + BOFF_H0L, BF + BOFF_WI0H, BF + BOFF_WI0L, b_ih_l0, GX0, M, 6 * F, F);

    // 4) Layer 0 recurrence
    zero_kernel<<<(int)((SZ_HG + SZ_BAR + 255) / 256), 256>>>(HG, (int)(SZ_HG + SZ_BAR));
    gru_layer_kernel<<<NBLK, PT, STEP_SMEM>>>(WT0, b_hh_l0, GX0, Y0, HG, BAR);
    split_kernel<<<nb(SZ_Ye), 256>>>(Y0, BF + BOFF_Y0H, BF + BOFF_Y0L, (int)SZ_Ye);

    // 5) Layer 1: gx  [8192,6144,K=2048]
    transpose_w_kernel<<<dim3(3 * F / 32, F / 32, 2), dim3(32, 8)>>>(w_hh_l1, WT1);
    gemm_bf16_split_kernel<<<dim3(6 * F / 128, M / 128), 256, SMEM_GEMM>>>(
        BF + BOFF_Y0H, BF + BOFF_Y0L, BF + BOFF_WI1H, BF + BOFF_WI1L, b_ih_l1, GX1, M, 6 * F, 2 * F);

    // 6) Layer 1 recurrence
    zero_kernel<<<(int)((SZ_HG + SZ_BAR + 255) / 256), 256>>>(HG, (int)(SZ_HG + SZ_BAR));
    gru_layer_kernel<<<NBLK, PT, STEP_SMEM>>>(WT1, b_hh_l1, GX1, Y1, HG, BAR);
    split_kernel<<<nb(SZ_Ye), 256>>>(Y1, BF + BOFF_Y1H, BF + BOFF_Y1L, (int)SZ_Ye);

    // 7) Output projection  [8192,1024,K=2048]
    gemm_bf16_split_kernel<<<dim3(OUTD / 128, M / 128), 256, SMEM_GEMM>>>(
        BF + BOFF_Y1H, BF + BOFF_Y1L, BF + BOFF_WOH, BF + BOFF_WOL, b_out, OUTT, M, OUTD, 2 * F);

    // 8) Final transpose
    transpose_out_kernel<<<dim3(Tt / 32, OUTD / 32, Bb), dim3(32, 8)>>>(OUTT, out);
}

// round 4
// speedup vs baseline: 3.5242x; 2.8549x over previous
#include <cuda_runtime.h>
#include <cuda_bf16.h>
#include <cstddef>

// Problem constants
constexpr int Tt   = 512;
constexpr int Bb   = 16;
constexpr int F    = 1024;   // FEAT
constexpr int INP  = 2048;
constexpr int OUTD = 1024;

constexpr int NBLK = 128;

// ---------------------------------------------------------------------------
// Float scratch
// ---------------------------------------------------------------------------
constexpr size_t OFF_X    = 0;
constexpr size_t SZ_X     = (size_t)Tt * Bb * INP;
constexpr size_t OFF_H0   = OFF_X + SZ_X;
constexpr size_t SZ_H0    = (size_t)Tt * Bb * F;
constexpr size_t OFF_GX0  = OFF_H0 + SZ_H0;
constexpr size_t SZ_GX    = (size_t)Tt * Bb * 6 * F;
constexpr size_t OFF_Y0   = OFF_GX0 + SZ_GX;
constexpr size_t SZ_Y     = (size_t)Tt * Bb * 2 * F;
constexpr size_t OFF_GX1  = OFF_Y0 + SZ_Y;
constexpr size_t OFF_Y1   = OFF_GX1 + SZ_GX;
constexpr size_t OFF_OUTT = OFF_Y1 + SZ_Y;
constexpr size_t SZ_OUTT  = (size_t)Tt * Bb * OUTD;
// W_hh fragment planes (uint32 views): [dir2][blk64][tile6][kstep64][lane32][reg2]
constexpr size_t SZ_WFp   = (size_t)2 * 64 * 6 * 64 * 32 * 2;   // 3145728
constexpr size_t OFF_WFH  = OFF_OUTT + SZ_OUTT;
constexpr size_t OFF_WFL  = OFF_WFH + SZ_WFp;
// h fragments: [parity2][dir2][plane2][kstep64][lane32][reg4] u32
constexpr size_t SZ_HF    = (size_t)2 * 2 * 2 * 64 * 32 * 4;    // 65536
constexpr size_t OFF_HF   = OFF_WFL + SZ_WFp;
constexpr size_t OFF_BAR  = OFF_HF + SZ_HF;
constexpr size_t SZ_BAR   = 16;
constexpr size_t SCRATCH_TOTAL = OFF_BAR + SZ_BAR;

__device__ float g_scratch[SCRATCH_TOTAL];

// ---------------------------------------------------------------------------
// bf16 scratch (hi/lo split planes) for projection GEMMs
// ---------------------------------------------------------------------------
constexpr size_t SZ_Xe   = (size_t)Tt * Bb * INP;
constexpr size_t SZ_H0e  = (size_t)Tt * Bb * F;
constexpr size_t SZ_Ye   = (size_t)Tt * Bb * 2 * F;
constexpr size_t SZ_WINe = (size_t)F * INP;
constexpr size_t SZ_WI0e = (size_t)6 * F * F;
constexpr size_t SZ_WI1e = (size_t)6 * F * 2 * F;
constexpr size_t SZ_WOe  = (size_t)OUTD * 2 * F;

constexpr size_t BOFF_XH  = 0;
constexpr size_t BOFF_XL  = BOFF_XH  + SZ_Xe;
constexpr size_t BOFF_H0H = BOFF_XL  + SZ_Xe;
constexpr size_t BOFF_H0L = BOFF_H0H + SZ_H0e;
constexpr size_t BOFF_Y0H = BOFF_H0L + SZ_H0e;
constexpr size_t BOFF_Y0L = BOFF_Y0H + SZ_Ye;
constexpr size_t BOFF_Y1H = BOFF_Y0L + SZ_Ye;
constexpr size_t BOFF_Y1L = BOFF_Y1H + SZ_Ye;
constexpr size_t BOFF_WINH= BOFF_Y1L + SZ_Ye;
constexpr size_t BOFF_WINL= BOFF_WINH+ SZ_WINe;
constexpr size_t BOFF_WI0H= BOFF_WINL+ SZ_WINe;
constexpr size_t BOFF_WI0L= BOFF_WI0H+ SZ_WI0e;
constexpr size_t BOFF_WI1H= BOFF_WI0L+ SZ_WI0e;
constexpr size_t BOFF_WI1L= BOFF_WI1H+ SZ_WI1e;
constexpr size_t BOFF_WOH = BOFF_WI1L+ SZ_WI1e;
constexpr size_t BOFF_WOL = BOFF_WOH + SZ_WOe;
constexpr size_t BF_TOTAL = BOFF_WOL + SZ_WOe;

__device__ __nv_bfloat16 g_bf[BF_TOTAL];

// ---------------------------------------------------------------------------
__global__ void split_kernel(const float* __restrict__ x,
                             __nv_bfloat16* __restrict__ h,
                             __nv_bfloat16* __restrict__ l, int n)
{
    int i = blockIdx.x * blockDim.x + threadIdx.x;
    if (i < n) {
        float v = x[i];
        __nv_bfloat16 hi = __float2bfloat16(v);
        float r = v - __bfloat162float(hi);
        h[i] = hi;
        l[i] = __float2bfloat16(r);
    }
}

// ---------------------------------------------------------------------------
__global__ void transpose_in_kernel(const float* __restrict__ in, float* __restrict__ out) {
    __shared__ float tile[32][33];
    int b  = blockIdx.z;
    int t0 = blockIdx.x * 32;
    int i0 = blockIdx.y * 32;
    int tx = threadIdx.x, ty = threadIdx.y;
#pragma unroll
    for (int j = 0; j < 32; j += 8)
        tile[ty + j][tx] = in[((size_t)b * INP + (i0 + ty + j)) * Tt + t0 + tx];
    __syncthreads();
#pragma unroll
    for (int j = 0; j < 32; j += 8)
        out[((size_t)(t0 + ty + j) * Bb + b) * INP + i0 + tx] = tile[tx][ty + j];
}

__global__ void transpose_out_kernel(const float* __restrict__ in, float* __restrict__ out) {
    __shared__ float tile[32][33];
    int b  = blockIdx.z;
    int t0 = blockIdx.x * 32;
    int o0 = blockIdx.y * 32;
    int tx = threadIdx.x, ty = threadIdx.y;
#pragma unroll
    for (int j = 0; j < 32; j += 8)
        tile[ty + j][tx] = in[((size_t)(t0 + ty + j) * Bb + b) * OUTD + o0 + tx];
    __syncthreads();
#pragma unroll
    for (int j = 0; j < 32; j += 8)
        out[((size_t)b * OUTD + (o0 + ty + j)) * Tt + t0 + tx] = tile[tx][ty + j];
}

// ---------------------------------------------------------------------------
// Tensor-core split-bf16 GEMM (unchanged from R3)
// ---------------------------------------------------------------------------
constexpr int TW  = 56;
constexpr int PL  = 128 * TW;
constexpr int GBUF = 4 * PL;
constexpr int SMEM_GEMM = 2 * GBUF * (int)sizeof(__nv_bfloat16);

__device__ __forceinline__ void cpa16(void* sdst, const void* gsrc) {
    unsigned s = (unsigned)__cvta_generic_to_shared(sdst);
    asm volatile("cp.async.cg.shared.global [%0], [%1], 16;\n" :: "r"(s), "l"(gsrc));
}
__device__ __forceinline__ void cpa_commit() {
    asm volatile("cp.async.commit_group;\n" ::);
}
__device__ __forceinline__ void cpa_wait0() {
    asm volatile("cp.async.wait_group 0;\n" ::);
}
__device__ __forceinline__ void mma_bf16(float* c, const unsigned* a, const unsigned* b) {
    asm volatile(
        "mma.sync.aligned.m16n8k16.row.col.f32.bf16.bf16.f32 "
        "{%0,%1,%2,%3},{%4,%5,%6,%7},{%8,%9},{%0,%1,%2,%3};\n"
        : "+f"(c[0]), "+f"(c[1]), "+f"(c[2]), "+f"(c[3])
        : "r"(a[0]), "r"(a[1]), "r"(a[2]), "r"(a[3]), "r"(b[0]), "r"(b[1]));
}

__global__ void __launch_bounds__(256) gemm_bf16_split_kernel(
    const __nv_bfloat16* __restrict__ Ah, const __nv_bfloat16* __restrict__ Al,
    const __nv_bfloat16* __restrict__ Wh, const __nv_bfloat16* __restrict__ Wl,
    const float* __restrict__ bias, float* __restrict__ C,
    int M, int N, int K)
{
    extern __shared__ __nv_bfloat16 smx[];
    const int tid = threadIdx.x;
    const int bm = blockIdx.y * 128, bn = blockIdx.x * 128;
    const int lane = tid & 31, wid = tid >> 5;
    const int wm = wid & 1, wn = wid >> 1;
    const int g = lane >> 2, t = lane & 3;

    float acc[4][4][4];
#pragma unroll
    for (int i = 0; i < 4; ++i)
#pragma unroll
        for (int j = 0; j < 4; ++j)
#pragma unroll
            for (int q = 0; q < 4; ++q) acc[i][j][q] = 0.f;

    const int r0 = tid >> 2;
    const int c0 = (tid & 3) * 8;
    const int nk = K / 32;

    {
        __nv_bfloat16* s = smx;
#pragma unroll
        for (int p = 0; p < 2; ++p) {
            int row = r0 + p * 64;
            size_t ga = (size_t)(bm + row) * K + c0;
            size_t gw = (size_t)(bn + row) * K + c0;
            int so = row * TW + c0;
            cpa16(s + 0 * PL + so, Ah + ga);
            cpa16(s + 1 * PL + so, Al + ga);
            cpa16(s + 2 * PL + so, Wh + gw);
            cpa16(s + 3 * PL + so, Wl + gw);
        }
        cpa_commit();
    }

    for (int kt = 0; kt < nk; ++kt) {
        cpa_wait0();
        __syncthreads();

        if (kt + 1 < nk) {
            __nv_bfloat16* s = smx + ((kt + 1) & 1) * GBUF;
            int k0 = (kt + 1) * 32;
#pragma unroll
            for (int p = 0; p < 2; ++p) {
                int row = r0 + p * 64;
                size_t ga = (size_t)(bm + row) * K + k0 + c0;
                size_t gw = (size_t)(bn + row) * K + k0 + c0;
                int so = row * TW + c0;
                cpa16(s + 0 * PL + so, Ah + ga);
                cpa16(s + 1 * PL + so, Al + ga);
                cpa16(s + 2 * PL + so, Wh + gw);
                cpa16(s + 3 * PL + so, Wl + gw);
            }
            cpa_commit();
        }

        const __nv_bfloat16* sb = smx + (kt & 1) * GBUF;
        const unsigned* pAh = (const unsigned*)(sb + 0 * PL);
        const unsigned* pAl = (const unsigned*)(sb + 1 * PL);
        const unsigned* pWh = (const unsigned*)(sb + 2 * PL);
        const unsigned* pWl = (const unsigned*)(sb + 3 * PL);

#pragma unroll
        for (int ks = 0; ks < 2; ++ks) {
            unsigned aH[4][4], aL[4][4], bH[4][2], bL[4][2];
#pragma unroll
            for (int i = 0; i < 4; ++i) {
                int rb = (wm * 64 + i * 16 + g) * 28 + ks * 8 + t;
                aH[i][0] = pAh[rb];           aH[i][2] = pAh[rb + 4];
                aH[i][1] = pAh[rb + 8 * 28];  aH[i][3] = pAh[rb + 8 * 28 + 4];
                aL[i][0] = pAl[rb];           aL[i][2] = pAl[rb + 4];
                aL[i][1] = pAl[rb + 8 * 28];  aL[i][3] = pAl[rb + 8 * 28 + 4];
            }
#pragma unroll
            for (int j = 0; j < 4; ++j) {
                int rb = (wn * 32 + j * 8 + g) * 28 + ks * 8 + t;
                bH[j][0] = pWh[rb]; bH[j][1] = pWh[rb + 4];
                bL[j][0] = pWl[rb]; bL[j][1] = pWl[rb + 4];
            }
#pragma unroll
            for (int i = 0; i < 4; ++i)
#pragma unroll
                for (int j = 0; j < 4; ++j) {
                    mma_bf16(acc[i][j], aH[i], bH[j]);
                    mma_bf16(acc[i][j], aH[i], bL[j]);
                    mma_bf16(acc[i][j], aL[i], bH[j]);
                }
        }
    }

#pragma unroll
    for (int i = 0; i < 4; ++i) {
        int row0 = bm + wm * 64 + i * 16 + g;
#pragma unroll
        for (int j = 0; j < 4; ++j) {
            int col = bn + wn * 32 + j * 8 + t * 2;
            float b0 = bias[col], b1 = bias[col + 1];
            float2 v0 = make_float2(acc[i][j][0] + b0, acc[i][j][1] + b1);
            float2 v1 = make_float2(acc[i][j][2] + b0, acc[i][j][3] + b1);
            *(float2*)(C + (size_t)row0 * N + col) = v0;
            *(float2*)(C + (size_t)(row0 + 8) * N + col) = v1;
        }
    }
}

// ---------------------------------------------------------------------------
__global__ void zero_kernel(float* p, int n) {
    int i = blockIdx.x * blockDim.x + threadIdx.x;
    if (i < n) p[i] = 0.f;
}

// ---------------------------------------------------------------------------
// Prepack W_hh [dir][3F][F] fp32 -> B-fragment bf16 hi/lo planes.
// idx = ((((d*64+blk)*6+t)*64+ks)*32+l)*2 + r
// row = g*1024 + blk*16 + half*8 + (l>>2),  k = ks*16 + r*8 + (l&3)*2
// ---------------------------------------------------------------------------
__global__ void prepack_whh_kernel(const float* __restrict__ whh,
                                   unsigned* __restrict__ wfh,
                                   unsigned* __restrict__ wfl)
{
    size_t i = (size_t)blockIdx.x * 256 + threadIdx.x;
    size_t i2 = i;
    int r   = (int)(i2 & 1);  i2 >>= 1;
    int l   = (int)(i2 & 31); i2 >>= 5;
    int ks  = (int)(i2 & 63); i2 >>= 6;
    int t   = (int)(i2 % 6);  i2 /= 6;
    int blk = (int)(i2 & 63); i2 >>= 6;
    int d   = (int)i2;
    int g = t >> 1, half = t & 1;
    int row = g * 1024 + blk * 16 + half * 8 + (l >> 2);
    int k   = ks * 16 + r * 8 + (l & 3) * 2;
    float w0 = whh[((size_t)d * 3072 + row) * 1024 + k];
    float w1 = whh[((size_t)d * 3072 + row) * 1024 + k + 1];
    __nv_bfloat16 h0 = __float2bfloat16(w0);
    __nv_bfloat16 h1 = __float2bfloat16(w1);
    __nv_bfloat16 l0 = __float2bfloat16(w0 - __bfloat162float(h0));
    __nv_bfloat16 l1 = __float2bfloat16(w1 - __bfloat162float(h1));
    wfh[i] = ((unsigned)__bfloat16_as_ushort(h1) << 16) | (unsigned)__bfloat16_as_ushort(h0);
    wfl[i] = ((unsigned)__bfloat16_as_ushort(l1) << 16) | (unsigned)__bfloat16_as_ushort(l0);
}

// ---------------------------------------------------------------------------
// Persistent tensor-core bidirectional GRU layer.
// 128 blocks (64/dir), 256 threads. Per block: 48 W rows (6 n8-tiles) resident
// in smem as mma B-fragments (hi/lo). h kept in global as A-fragments (hi/lo),
// double-buffered by step parity. Warps split K 8-way, reduce via smem.
// ---------------------------------------------------------------------------
constexpr int WS_U32 = 6 * 64 * 32 * 2;   // 24576 u32 per plane
constexpr int REC_SMEM = (2 * WS_U32) * 4 + (8 * 768) * 4 + 768 * 4;  // 224256 B

__device__ __forceinline__ unsigned ld_acquire(const unsigned* p) {
    unsigned v;
    asm volatile("ld.global.acquire.gpu.u32 %0, [%1];" : "=r"(v) : "l"(p) : "memory");
    return v;
}

__global__ void __launch_bounds__(256, 1) gru_layer_tc_kernel(
    const unsigned* __restrict__ WFH, const unsigned* __restrict__ WFL,
    const float* __restrict__ bhh,    // [2][3F]
    const float* __restrict__ gx,     // [Tt*Bb][6F]
    float* __restrict__ y,            // [Tt][Bb][2][F]
    unsigned* __restrict__ HF,        // [parity2][dir2][plane2][64][32][4] u32
    unsigned* __restrict__ bar)
{
    extern __shared__ unsigned smu[];
    unsigned* wsH = smu;
    unsigned* wsL = smu + WS_U32;
    float* red = (float*)(smu + 2 * WS_U32);
    float* fin = red + 8 * 768;

    const int tid = threadIdx.x;
    const int dir = blockIdx.x >> 6;
    const int blk = blockIdx.x & 63;
    const int u0  = blk * 16;
    const int lane = tid & 31, w = tid >> 5;

    // Load W fragment chunk (contiguous) into smem once
    {
        const uint4* srcH = (const uint4*)(WFH + (size_t)(dir * 64 + blk) * WS_U32);
        const uint4* srcL = (const uint4*)(WFL + (size_t)(dir * 64 + blk) * WS_U32);
        uint4* dH = (uint4*)wsH;
        uint4* dL = (uint4*)wsL;
        for (int i = tid; i < WS_U32 / 4; i += 256) { dH[i] = srcH[i]; dL[i] = srcL[i]; }
    }

    // Gate-thread constants: b = tid>>4, u = tid&15 (unit fast -> coalesced y/gx)
    const int gb = tid >> 4;
    const int gu = tid & 15;
    const int gj = u0 + gu;
    const float br  = bhh[dir * 3072 + gj];
    const float bz  = bhh[dir * 3072 + 1024 + gj];
    const float bn2 = bhh[dir * 3072 + 2048 + gj];
    float hprev = 0.f;

    // HF write index (this block owns kstep = u0/16)
    const int ksb   = u0 >> 4;
    const int wlane = ((gb & 7) << 2) + ((gu & 7) >> 1);
    const int wreg  = ((gu >= 8) ? 2 : 0) + ((gb >= 8) ? 1 : 0);
    const int widx  = (ksb * 32 + wlane) * 4 + wreg;

    // fin read indices: t = g*2 + (gu>=8); l = wlane; c = (gu&1) + (gb>=8)*2
    const int fhalf = (gu >= 8) ? 1 : 0;
    const int foff  = wlane * 4 + (gu & 1) + ((gb >= 8) ? 2 : 0);

    __syncthreads();

    for (int s = 0; s < Tt; ++s) {
        const int cur = s & 1, nxt = cur ^ 1;
        const int tt  = dir ? (Tt - 1 - s) : s;

        // Prefetch gx (consumed after reduction)
        const float* gxp = gx + (size_t)(tt * 16 + gb) * 6144 + dir * 3072;
        float xr = __ldg(gxp + gj);
        float xz = __ldg(gxp + 1024 + gj);
        float xn = __ldg(gxp + 2048 + gj);

        // MMA phase: warp w covers ksteps [w*8, w*8+8)
        float acc[6][4];
#pragma unroll
        for (int t = 0; t < 6; ++t)
#pragma unroll
            for (int q = 0; q < 4; ++q) acc[t][q] = 0.f;

        const unsigned* hfH = HF + ((size_t)(cur * 2 + dir) * 2 + 0) * 8192;
        const unsigned* hfL = HF + ((size_t)(cur * 2 + dir) * 2 + 1) * 8192;

#pragma unroll
        for (int kk = 0; kk < 8; ++kk) {
            int ks = w * 8 + kk;
            uint4 AHv = __ldcg((const uint4*)(hfH + (ks * 32 + lane) * 4));
            uint4 ALv = __ldcg((const uint4*)(hfL + (ks * 32 + lane) * 4));
            unsigned aH[4] = {AHv.x, AHv.y, AHv.z, AHv.w};
            unsigned aL[4] = {ALv.x, ALv.y, ALv.z, ALv.w};
#pragma unroll
            for (int t = 0; t < 6; ++t) {
                int bi = ((t * 64 + ks) * 32 + lane) * 2;
                unsigned bH[2] = {wsH[bi], wsH[bi + 1]};
                unsigned bL[2] = {wsL[bi], wsL[bi + 1]};
                mma_bf16(acc[t], aH, bH);
                mma_bf16(acc[t], aL, bH);
                mma_bf16(acc[t], aH, bL);
            }
        }
#pragma unroll
        for (int t = 0; t < 6; ++t) {
            float4 v = make_float4(acc[t][0], acc[t][1], acc[t][2], acc[t][3]);
            *(float4*)&red[((w * 6 + t) * 32 + lane) * 4] = v;
        }
        __syncthreads();

        // Cross-warp reduction: 768 outputs
        for (int idx = tid; idx < 768; idx += 256) {
            float sum = 0.f;
#pragma unroll
            for (int ww = 0; ww < 8; ++ww) sum += red[ww * 768 + idx];
            fin[idx] = sum;
        }
        __syncthreads();

        // Gates + h update
        {
            float ghr = fin[(0 + fhalf) * 128 + foff] + br;
            float ghz = fin[(2 + fhalf) * 128 + foff] + bz;
            float ghn = fin[(4 + fhalf) * 128 + foff] + bn2;
            float r = 1.f / (1.f + expf(-(xr + ghr)));
            float z = 1.f / (1.f + expf(-(xz + ghz)));
            float n = tanhf(xn + r * ghn);
            float hnew = (1.f - z) * n + z * hprev;
            hprev = hnew;
            y[(size_t)(tt * 16 + gb) * 2048 + dir * 1024 + gj] = hnew;

            // Split hi/lo, pack k-pairs via shfl, write HF[nxt]
            __nv_bfloat16 hhi = __float2bfloat16(hnew);
            float rlo = hnew - __bfloat162float(hhi);
            __nv_bfloat16 hlo = __float2bfloat16(rlo);
            unsigned vh = (unsigned)__bfloat16_as_ushort(hhi);
            unsigned vl = (unsigned)__bfloat16_as_ushort(hlo);
            unsigned ph = __shfl_down_sync(0xffffffffu, vh, 1);
            unsigned pl = __shfl_down_sync(0xffffffffu, vl, 1);
            if ((gu & 1) == 0) {
                unsigned* oH = (unsigned*)(HF + ((size_t)(nxt * 2 + dir) * 2 + 0) * 8192);
                unsigned* oL = (unsigned*)(HF + ((size_t)(nxt * 2 + dir) * 2 + 1) * 8192);
                oH[widx] = (ph << 16) | vh;
                oL[widx] = (pl << 16) | vl;
            }
        }

        // Grid barrier
        __syncthreads();
        if (tid == 0) {
            __threadfence();
            atomicAdd(bar, 1u);
            unsigned tgt = (unsigned)(s + 1) * gridDim.x;
            while (ld_acquire(bar) < tgt) { }
            __threadfence();
        }
        __syncthreads();
    }
}

// ---------------------------------------------------------------------------
extern "C" void kernel_launch(void* const* d_in, const int* in_sizes, int n_in,
                              void* d_out, int out_size)
{
    const float* inp     = (const float*)d_in[0];
    const float* w_in    = (const float*)d_in[1];
    const float* b_in    = (const float*)d_in[2];
    const float* w_ih_l0 = (const float*)d_in[3];
    const float* w_hh_l0 = (const float*)d_in[4];
    const float* b_ih_l0 = (const float*)d_in[5];
    const float* b_hh_l0 = (const float*)d_in[6];
    const float* w_ih_l1 = (const float*)d_in[7];
    const float* w_hh_l1 = (const float*)d_in[8];
    const float* b_ih_l1 = (const float*)d_in[9];
    const float* b_hh_l1 = (const float*)d_in[10];
    const float* w_out   = (const float*)d_in[11];
    const float* b_out   = (const float*)d_in[12];
    float* out = (float*)d_out;

    float* S = nullptr;
    cudaGetSymbolAddress((void**)&S, g_scratch);
    __nv_bfloat16* BF = nullptr;
    cudaGetSymbolAddress((void**)&BF, g_bf);

    float* X    = S + OFF_X;
    float* H0   = S + OFF_H0;
    float* GX0  = S + OFF_GX0;
    float* Y0   = S + OFF_Y0;
    float* GX1  = S + OFF_GX1;
    float* Y1   = S + OFF_Y1;
    float* OUTT = S + OFF_OUTT;
    unsigned* WFH = (unsigned*)(S + OFF_WFH);
    unsigned* WFL = (unsigned*)(S + OFF_WFL);
    unsigned* HF  = (unsigned*)(S + OFF_HF);
    unsigned* BAR = (unsigned*)(S + OFF_BAR);

    cudaFuncSetAttribute(gemm_bf16_split_kernel,
                         cudaFuncAttributeMaxDynamicSharedMemorySize, SMEM_GEMM);
    cudaFuncSetAttribute(gru_layer_tc_kernel,
                         cudaFuncAttributeMaxDynamicSharedMemorySize, REC_SMEM);

    const int M = Tt * Bb;  // 8192
    auto nb = [](size_t n) { return (int)((n + 255) / 256); };
    const int WF_BLKS = (int)(SZ_WFp / 256);

    // 1) Transpose input + split
    transpose_in_kernel<<<dim3(Tt / 32, INP / 32, Bb), dim3(32, 8)>>>(inp, X);
    split_kernel<<<nb(SZ_Xe), 256>>>(X, BF + BOFF_XH, BF + BOFF_XL, (int)SZ_Xe);

    // Weight splits
    split_kernel<<<nb(SZ_WINe), 256>>>(w_in,    BF + BOFF_WINH, BF + BOFF_WINL, (int)SZ_WINe);
    split_kernel<<<nb(SZ_WI0e), 256>>>(w_ih_l0, BF + BOFF_WI0H, BF + BOFF_WI0L, (int)SZ_WI0e);
    split_kernel<<<nb(SZ_WI1e), 256>>>(w_ih_l1, BF + BOFF_WI1H, BF + BOFF_WI1L, (int)SZ_WI1e);
    split_kernel<<<nb(SZ_WOe),  256>>>(w_out,   BF + BOFF_WOH,  BF + BOFF_WOL,  (int)SZ_WOe);

    // 2) Input projection
    gemm_bf16_split_kernel<<<dim3(F / 128, M / 128), 256, SMEM_GEMM>>>(
        BF + BOFF_XH, BF + BOFF_XL, BF + BOFF_WINH, BF + BOFF_WINL, b_in, H0, M, F, INP);
    split_kernel<<<nb(SZ_H0e), 256>>>(H0, BF + BOFF_H0H, BF + BOFF_H0L, (int)SZ_H0e);

    // 3) Layer 0: gx (both dirs) + W_hh prepack
    gemm_bf16_split_kernel<<<dim3(6 * F / 128, M / 128), 256, SMEM_GEMM>>>(
        BF + BOFF_H0H, BF + BOFF_H0L, BF + BOFF_WI0H, BF + BOFF_WI0L, b_ih_l0, GX0, M, 6 * F, F);
    prepack_whh_kernel<<<WF_BLKS, 256>>>(w_hh_l0, WFH, WFL);

    // 4) Layer 0 recurrence
    zero_kernel<<<nb(SZ_HF + 4), 256>>>(S + OFF_HF, (int)(SZ_HF + 4));
    gru_layer_tc_kernel<<<NBLK, 256, REC_SMEM>>>(WFH, WFL, b_hh_l0, GX0, Y0, HF, BAR);
    split_kernel<<<nb(SZ_Ye), 256>>>(Y0, BF + BOFF_Y0H, BF + BOFF_Y0L, (int)SZ_Ye);

    // 5) Layer 1: gx + prepack
    gemm_bf16_split_kernel<<<dim3(6 * F / 128, M / 128), 256, SMEM_GEMM>>>(
        BF + BOFF_Y0H, BF + BOFF_Y0L, BF + BOFF_WI1H, BF + BOFF_WI1L, b_ih_l1, GX1, M, 6 * F, 2 * F);
    prepack_whh_kernel<<<WF_BLKS, 256>>>(w_hh_l1, WFH, WFL);

    // 6) Layer 1 recurrence
    zero_kernel<<<nb(SZ_HF + 4), 256>>>(S + OFF_HF, (int)(SZ_HF + 4));
    gru_layer_tc_kernel<<<NBLK, 256, REC_SMEM>>>(WFH, WFL, b_hh_l1, GX1, Y1, HF, BAR);
    split_kernel<<<nb(SZ_Ye), 256>>>(Y1, BF + BOFF_Y1H, BF + BOFF_Y1L, (int)SZ_Ye);

    // 7) Output projection
    gemm_bf16_split_kernel<<<dim3(OUTD / 128, M / 128), 256, SMEM_GEMM>>>(
        BF + BOFF_Y1H, BF + BOFF_Y1L, BF + BOFF_WOH, BF + BOFF_WOL, b_out, OUTT, M, OUTD, 2 * F);

    // 8) Final transpose
    transpose_out_kernel<<<dim3(Tt / 32, OUTD / 32, Bb), dim3(32, 8)>>>(OUTT, out);
}

// round 5
// speedup vs baseline: 3.7301x; 1.0584x over previous
#include <cuda_runtime.h>
#include <cuda_bf16.h>
#include <cstddef>

// Problem constants
constexpr int Tt   = 512;
constexpr int Bb   = 16;
constexpr int F    = 1024;   // FEAT
constexpr int INP  = 2048;
constexpr int OUTD = 1024;

constexpr int NBLK = 128;

// ---------------------------------------------------------------------------
// Float/u32 scratch
// ---------------------------------------------------------------------------
constexpr size_t OFF_GX0  = 0;
constexpr size_t SZ_GX    = (size_t)Tt * Bb * 6 * F;
constexpr size_t OFF_GX1  = OFF_GX0 + SZ_GX;
constexpr size_t OFF_OUTT = OFF_GX1 + SZ_GX;
constexpr size_t SZ_OUTT  = (size_t)Tt * Bb * OUTD;
// W_hh fragment planes (u32): [dir2][blk64][tile6][kstep64][lane32][reg2]
constexpr size_t SZ_WFp   = (size_t)2 * 64 * 6 * 64 * 32 * 2;
constexpr size_t OFF_WFH  = OFF_OUTT + SZ_OUTT;
constexpr size_t OFF_WFL  = OFF_WFH + SZ_WFp;
// h fragments: [parity2][dir2][plane2][kstep64][lane32][reg4] u32
constexpr size_t SZ_HF    = (size_t)2 * 2 * 2 * 64 * 32 * 4;
constexpr size_t OFF_HF   = OFF_WFL + SZ_WFp;
constexpr size_t OFF_BAR  = OFF_HF + SZ_HF;     // 2 counters, 128B apart
constexpr size_t SZ_BAR   = 64;
constexpr size_t SCRATCH_TOTAL = OFF_BAR + SZ_BAR;

__device__ float g_scratch[SCRATCH_TOTAL];

// ---------------------------------------------------------------------------
// bf16 scratch (hi/lo planes)
// ---------------------------------------------------------------------------
constexpr size_t SZ_Xe   = (size_t)Tt * Bb * INP;
constexpr size_t SZ_H0e  = (size_t)Tt * Bb * F;
constexpr size_t SZ_Ye   = (size_t)Tt * Bb * 2 * F;
constexpr size_t SZ_WINe = (size_t)F * INP;
constexpr size_t SZ_WI0e = (size_t)6 * F * F;
constexpr size_t SZ_WI1e = (size_t)6 * F * 2 * F;
constexpr size_t SZ_WOe  = (size_t)OUTD * 2 * F;

constexpr size_t BOFF_XH  = 0;
constexpr size_t BOFF_XL  = BOFF_XH  + SZ_Xe;
constexpr size_t BOFF_H0H = BOFF_XL  + SZ_Xe;
constexpr size_t BOFF_H0L = BOFF_H0H + SZ_H0e;
constexpr size_t BOFF_Y0H = BOFF_H0L + SZ_H0e;
constexpr size_t BOFF_Y0L = BOFF_Y0H + SZ_Ye;
constexpr size_t BOFF_Y1H = BOFF_Y0L + SZ_Ye;
constexpr size_t BOFF_Y1L = BOFF_Y1H + SZ_Ye;
constexpr size_t BOFF_WINH= BOFF_Y1L + SZ_Ye;
constexpr size_t BOFF_WINL= BOFF_WINH+ SZ_WINe;
constexpr size_t BOFF_WI0H= BOFF_WINL+ SZ_WINe;
constexpr size_t BOFF_WI0L= BOFF_WI0H+ SZ_WI0e;
constexpr size_t BOFF_WI1H= BOFF_WI0L+ SZ_WI0e;
constexpr size_t BOFF_WI1L= BOFF_WI1H+ SZ_WI1e;
constexpr size_t BOFF_WOH = BOFF_WI1L+ SZ_WI1e;
constexpr size_t BOFF_WOL = BOFF_WOH + SZ_WOe;
constexpr size_t BF_TOTAL = BOFF_WOL + SZ_WOe;

__device__ __nv_bfloat16 g_bf[BF_TOTAL];

// ---------------------------------------------------------------------------
__device__ __forceinline__ void split_store(float v, __nv_bfloat16* h, __nv_bfloat16* l) {
    __nv_bfloat16 hi = __float2bfloat16(v);
    *h = hi;
    *l = __float2bfloat16(v - __bfloat162float(hi));
}

// Transpose + split: inp [B][INP][T] -> XH/XL [T*B][INP]
__global__ void transpose_in_split_kernel(const float* __restrict__ in,
                                          __nv_bfloat16* __restrict__ XH,
                                          __nv_bfloat16* __restrict__ XL)
{
    __shared__ float tile[32][33];
    int b  = blockIdx.z;
    int t0 = blockIdx.x * 32;
    int i0 = blockIdx.y * 32;
    int tx = threadIdx.x, ty = threadIdx.y;
#pragma unroll
    for (int j = 0; j < 32; j += 8)
        tile[ty + j][tx] = in[((size_t)b * INP + (i0 + ty + j)) * Tt + t0 + tx];
    __syncthreads();
#pragma unroll
    for (int j = 0; j < 32; j += 8) {
        size_t o = ((size_t)(t0 + ty + j) * Bb + b) * INP + i0 + tx;
        split_store(tile[tx][ty + j], XH + o, XL + o);
    }
}

__global__ void transpose_out_kernel(const float* __restrict__ in, float* __restrict__ out) {
    __shared__ float tile[32][33];
    int b  = blockIdx.z;
    int t0 = blockIdx.x * 32;
    int o0 = blockIdx.y * 32;
    int tx = threadIdx.x, ty = threadIdx.y;
#pragma unroll
    for (int j = 0; j < 32; j += 8)
        tile[ty + j][tx] = in[((size_t)(t0 + ty + j) * Bb + b) * OUTD + o0 + tx];
    __syncthreads();
#pragma unroll
    for (int j = 0; j < 32; j += 8)
        out[((size_t)b * OUTD + (o0 + ty + j)) * Tt + t0 + tx] = tile[tx][ty + j];
}

// All four weight splits in one kernel
__global__ void wsplit_all_kernel(const float* __restrict__ a, const float* __restrict__ b,
                                  const float* __restrict__ c, const float* __restrict__ d,
                                  __nv_bfloat16* __restrict__ BF)
{
    size_t i = (size_t)blockIdx.x * 256 + threadIdx.x;
    const float* src; size_t hoff, loff, idx;
    if (i < SZ_WINe) {
        src = a; idx = i; hoff = BOFF_WINH + i; loff = BOFF_WINL + i;
    } else if (i < SZ_WINe + SZ_WI0e) {
        idx = i - SZ_WINe; src = b; hoff = BOFF_WI0H + idx; loff = BOFF_WI0L + idx;
    } else if (i < SZ_WINe + SZ_WI0e + SZ_WI1e) {
        idx = i - SZ_WINe - SZ_WI0e; src = c; hoff = BOFF_WI1H + idx; loff = BOFF_WI1L + idx;
    } else if (i < SZ_WINe + SZ_WI0e + SZ_WI1e + SZ_WOe) {
        idx = i - SZ_WINe - SZ_WI0e - SZ_WI1e; src = d; hoff = BOFF_WOH + idx; loff = BOFF_WOL + idx;
    } else return;
    split_store(src[idx], BF + hoff, BF + loff);
}

// ---------------------------------------------------------------------------
// Tensor-core split-bf16 GEMM with ldmatrix fragment loads.
// C = A*W^T + bias; optional bf16 hi/lo split output.
// ---------------------------------------------------------------------------
constexpr int TW  = 56;            // bf16 per smem row (7x16B, odd -> ldsm conflict-free)
constexpr int PL  = 128 * TW;
constexpr int GBUF = 4 * PL;
constexpr int SMEM_GEMM = 2 * GBUF * (int)sizeof(__nv_bfloat16);

__device__ __forceinline__ void cpa16(void* sdst, const void* gsrc) {
    unsigned s = (unsigned)__cvta_generic_to_shared(sdst);
    asm volatile("cp.async.cg.shared.global [%0], [%1], 16;\n" :: "r"(s), "l"(gsrc));
}
__device__ __forceinline__ void cpa_commit() {
    asm volatile("cp.async.commit_group;\n" ::);
}
__device__ __forceinline__ void cpa_wait0() {
    asm volatile("cp.async.wait_group 0;\n" ::);
}
__device__ __forceinline__ void mma_bf16(float* c, const unsigned* a, const unsigned* b) {
    asm volatile(
        "mma.sync.aligned.m16n8k16.row.col.f32.bf16.bf16.f32 "
        "{%0,%1,%2,%3},{%4,%5,%6,%7},{%8,%9},{%0,%1,%2,%3};\n"
        : "+f"(c[0]), "+f"(c[1]), "+f"(c[2]), "+f"(c[3])
        : "r"(a[0]), "r"(a[1]), "r"(a[2]), "r"(a[3]), "r"(b[0]), "r"(b[1]));
}
__device__ __forceinline__ void ldsm4(unsigned* r, const __nv_bfloat16* p) {
    unsigned a = (unsigned)__cvta_generic_to_shared(p);
    asm volatile("ldmatrix.sync.aligned.m8n8.x4.shared.b16 {%0,%1,%2,%3},[%4];\n"
        : "=r"(r[0]), "=r"(r[1]), "=r"(r[2]), "=r"(r[3]) : "r"(a));
}
__device__ __forceinline__ void ldsm2(unsigned* r, const __nv_bfloat16* p) {
    unsigned a = (unsigned)__cvta_generic_to_shared(p);
    asm volatile("ldmatrix.sync.aligned.m8n8.x2.shared.b16 {%0,%1},[%2];\n"
        : "=r"(r[0]), "=r"(r[1]) : "r"(a));
}

__global__ void __launch_bounds__(256) gemm_bf16_split_kernel(
    const __nv_bfloat16* __restrict__ Ah, const __nv_bfloat16* __restrict__ Al,
    const __nv_bfloat16* __restrict__ Wh, const __nv_bfloat16* __restrict__ Wl,
    const float* __restrict__ bias,
    float* __restrict__ C,                       // fp32 out (may be null)
    __nv_bfloat16* __restrict__ CH, __nv_bfloat16* __restrict__ CL,  // split out (may be null)
    int M, int N, int K)
{
    extern __shared__ __nv_bfloat16 smx[];
    const int tid = threadIdx.x;
    const int bm = blockIdx.y * 128, bn = blockIdx.x * 128;
    const int lane = tid & 31, wid = tid >> 5;
    const int wm = wid & 1, wn = wid >> 1;
    const int g = lane >> 2, t = lane & 3;

    float acc[4][4][4];
#pragma unroll
    for (int i = 0; i < 4; ++i)
#pragma unroll
        for (int j = 0; j < 4; ++j)
#pragma unroll
            for (int q = 0; q < 4; ++q) acc[i][j][q] = 0.f;

    const int r0 = tid >> 2;
    const int c0 = (tid & 3) * 8;
    const int nk = K / 32;

    // ldmatrix per-lane base offsets (bf16 units)
    const int aOff = (wm * 64 + (lane & 7) + ((lane >> 3) & 1) * 8) * TW + (lane >> 4) * 8;
    const int lb = lane & 15;
    const int bOff = (wn * 32 + (lb & 7)) * TW + ((lb >> 3) & 1) * 8;

    {
        __nv_bfloat16* s = smx;
#pragma unroll
        for (int p = 0; p < 2; ++p) {
            int row = r0 + p * 64;
            size_t ga = (size_t)(bm + row) * K + c0;
            size_t gw = (size_t)(bn + row) * K + c0;
            int so = row * TW + c0;
            cpa16(s + 0 * PL + so, Ah + ga);
            cpa16(s + 1 * PL + so, Al + ga);
            cpa16(s + 2 * PL + so, Wh + gw);
            cpa16(s + 3 * PL + so, Wl + gw);
        }
        cpa_commit();
    }

    for (int kt = 0; kt < nk; ++kt) {
        cpa_wait0();
        __syncthreads();

        if (kt + 1 < nk) {
            __nv_bfloat16* s = smx + ((kt + 1) & 1) * GBUF;
            int k0 = (kt + 1) * 32;
#pragma unroll
            for (int p = 0; p < 2; ++p) {
                int row = r0 + p * 64;
                size_t ga = (size_t)(bm + row) * K + k0 + c0;
                size_t gw = (size_t)(bn + row) * K + k0 + c0;
                int so = row * TW + c0;
                cpa16(s + 0 * PL + so, Ah + ga);
                cpa16(s + 1 * PL + so, Al + ga);
                cpa16(s + 2 * PL + so, Wh + gw);
                cpa16(s + 3 * PL + so, Wl + gw);
            }
            cpa_commit();
        }

        const __nv_bfloat16* sb = smx + (kt & 1) * GBUF;

#pragma unroll
        for (int ks = 0; ks < 2; ++ks) {
            unsigned aH[4][4], aL[4][4], bH[4][2], bL[4][2];
#pragma unroll
            for (int i = 0; i < 4; ++i) {
                int off = aOff + i * 16 * TW + ks * 16;
                ldsm4(aH[i], sb + 0 * PL + off);
                ldsm4(aL[i], sb + 1 * PL + off);
            }
#pragma unroll
            for (int j = 0; j < 4; ++j) {
                int off = bOff + j * 8 * TW + ks * 16;
                ldsm2(bH[j], sb + 2 * PL + off);
                ldsm2(bL[j], sb + 3 * PL + off);
            }
#pragma unroll
            for (int i = 0; i < 4; ++i)
#pragma unroll
                for (int j = 0; j < 4; ++j) {
                    mma_bf16(acc[i][j], aH[i], bH[j]);
                    mma_bf16(acc[i][j], aH[i], bL[j]);
                    mma_bf16(acc[i][j], aL[i], bH[j]);
                }
        }
    }

    // Epilogue
#pragma unroll
    for (int i = 0; i < 4; ++i) {
        int row0 = bm + wm * 64 + i * 16 + g;
#pragma unroll
        for (int j = 0; j < 4; ++j) {
            int col = bn + wn * 32 + j * 8 + t * 2;
            float b0 = bias[col], b1 = bias[col + 1];
            float v00 = acc[i][j][0] + b0, v01 = acc[i][j][1] + b1;
            float v10 = acc[i][j][2] + b0, v11 = acc[i][j][3] + b1;
            if (CH) {
                size_t p0 = (size_t)row0 * N + col;
                size_t p1 = (size_t)(row0 + 8) * N + col;
                __nv_bfloat16 h00 = __float2bfloat16(v00), h01 = __float2bfloat16(v01);
                __nv_bfloat16 h10 = __float2bfloat16(v10), h11 = __float2bfloat16(v11);
                *(__nv_bfloat162*)(CH + p0) = __nv_bfloat162(h00, h01);
                *(__nv_bfloat162*)(CH + p1) = __nv_bfloat162(h10, h11);
                *(__nv_bfloat162*)(CL + p0) = __nv_bfloat162(
                    __float2bfloat16(v00 - __bfloat162float(h00)),
                    __float2bfloat16(v01 - __bfloat162float(h01)));
                *(__nv_bfloat162*)(CL + p1) = __nv_bfloat162(
                    __float2bfloat16(v10 - __bfloat162float(h10)),
                    __float2bfloat16(v11 - __bfloat162float(h11)));
            } else {
                *(float2*)(C + (size_t)row0 * N + col) = make_float2(v00, v01);
                *(float2*)(C + (size_t)(row0 + 8) * N + col) = make_float2(v10, v11);
            }
        }
    }
}

// ---------------------------------------------------------------------------
// Prepack W_hh fp32 -> B-fragment bf16 hi/lo planes. Also zeros HF + counters.
// ---------------------------------------------------------------------------
__global__ void prepack_whh_kernel(const float* __restrict__ whh,
                                   unsigned* __restrict__ wfh,
                                   unsigned* __restrict__ wfl,
                                   unsigned* __restrict__ hf,
                                   unsigned* __restrict__ bar)
{
    if (blockIdx.x < 64) {
#pragma unroll
        for (int k = 0; k < 4; ++k)
            hf[blockIdx.x * 1024 + k * 256 + threadIdx.x] = 0;
    }
    if (blockIdx.x == 64 && threadIdx.x < 16) bar[threadIdx.x] = 0;

    size_t i = (size_t)blockIdx.x * 256 + threadIdx.x;
    size_t i2 = i;
    int r   = (int)(i2 & 1);  i2 >>= 1;
    int l   = (int)(i2 & 31); i2 >>= 5;
    int ks  = (int)(i2 & 63); i2 >>= 6;
    int t   = (int)(i2 % 6);  i2 /= 6;
    int blk = (int)(i2 & 63); i2 >>= 6;
    int d   = (int)i2;
    int g = t >> 1, half = t & 1;
    int row = g * 1024 + blk * 16 + half * 8 + (l >> 2);
    int k   = ks * 16 + r * 8 + (l & 3) * 2;
    float w0 = whh[((size_t)d * 3072 + row) * 1024 + k];
    float w1 = whh[((size_t)d * 3072 + row) * 1024 + k + 1];
    __nv_bfloat16 h0 = __float2bfloat16(w0);
    __nv_bfloat16 h1 = __float2bfloat16(w1);
    __nv_bfloat16 l0 = __float2bfloat16(w0 - __bfloat162float(h0));
    __nv_bfloat16 l1 = __float2bfloat16(w1 - __bfloat162float(h1));
    wfh[i] = ((unsigned)__bfloat16_as_ushort(h1) << 16) | (unsigned)__bfloat16_as_ushort(h0);
    wfl[i] = ((unsigned)__bfloat16_as_ushort(l1) << 16) | (unsigned)__bfloat16_as_ushort(l0);
}

// ---------------------------------------------------------------------------
// Persistent tensor-core bidirectional GRU layer (per-dir barrier, fused reduce)
// ---------------------------------------------------------------------------
constexpr int WS_U32 = 6 * 64 * 32 * 2;
constexpr int REC_SMEM = (2 * WS_U32) * 4 + (8 * 768) * 4;   // 221184 B

__device__ __forceinline__ unsigned ld_acquire(const unsigned* p) {
    unsigned v;
    asm volatile("ld.global.acquire.gpu.u32 %0, [%1];" : "=r"(v) : "l"(p) : "memory");
    return v;
}
__device__ __forceinline__ void red_release_add(unsigned* p, unsigned v) {
    asm volatile("red.release.gpu.global.add.u32 [%0], %1;" :: "l"(p), "r"(v) : "memory");
}

__global__ void __launch_bounds__(256, 1) gru_layer_tc_kernel(
    const unsigned* __restrict__ WFH, const unsigned* __restrict__ WFL,
    const float* __restrict__ bhh,
    const float* __restrict__ gx,      // [Tt*Bb][6F]
    __nv_bfloat16* __restrict__ YH, __nv_bfloat16* __restrict__ YL,  // [Tt*Bb][2F]
    unsigned* __restrict__ HF,
    unsigned* __restrict__ bar)
{
    extern __shared__ unsigned smu[];
    unsigned* wsH = smu;
    unsigned* wsL = smu + WS_U32;
    float* red = (float*)(smu + 2 * WS_U32);

    const int tid = threadIdx.x;
    const int dir = blockIdx.x >> 6;
    const int blk = blockIdx.x & 63;
    const int u0  = blk * 16;
    const int lane = tid & 31, w = tid >> 5;
    unsigned* bard = bar + dir * 32;

    {
        const uint4* srcH = (const uint4*)(WFH + (size_t)(dir * 64 + blk) * WS_U32);
        const uint4* srcL = (const uint4*)(WFL + (size_t)(dir * 64 + blk) * WS_U32);
        uint4* dH = (uint4*)wsH;
        uint4* dL = (uint4*)wsL;
        for (int i = tid; i < WS_U32 / 4; i += 256) { dH[i] = srcH[i]; dL[i] = srcL[i]; }
    }

    const int gb = tid >> 4;
    const int gu = tid & 15;
    const int gj = u0 + gu;
    const float br  = bhh[dir * 3072 + gj];
    const float bz  = bhh[dir * 3072 + 1024 + gj];
    const float bn2 = bhh[dir * 3072 + 2048 + gj];
    float hprev = 0.f;

    const int ksb   = u0 >> 4;
    const int wlane = ((gb & 7) << 2) + ((gu & 7) >> 1);
    const int wreg  = ((gu >= 8) ? 2 : 0) + ((gb >= 8) ? 1 : 0);
    const int widx  = (ksb * 32 + wlane) * 4 + wreg;

    const int fhalf = (gu >= 8) ? 1 : 0;
    const int foff  = fhalf * 128 + wlane * 4 + (gu & 1) + ((gb >= 8) ? 2 : 0);

    __syncthreads();

    for (int s = 0; s < Tt; ++s) {
        const int cur = s & 1, nxt = cur ^ 1;
        const int tt  = dir ? (Tt - 1 - s) : s;

        const float* gxp = gx + (size_t)(tt * 16 + gb) * 6144 + dir * 3072;
        float xr = __ldg(gxp + gj);
        float xz = __ldg(gxp + 1024 + gj);
        float xn = __ldg(gxp + 2048 + gj);

        float acc[6][4];
#pragma unroll
        for (int t = 0; t < 6; ++t)
#pragma unroll
            for (int q = 0; q < 4; ++q) acc[t][q] = 0.f;

        const unsigned* hfH = HF + ((size_t)(cur * 2 + dir) * 2 + 0) * 8192;
        const unsigned* hfL = HF + ((size_t)(cur * 2 + dir) * 2 + 1) * 8192;

#pragma unroll
        for (int kk = 0; kk < 8; ++kk) {
            int ks = w * 8 + kk;
            uint4 AHv = __ldcg((const uint4*)(hfH + (ks * 32 + lane) * 4));
            uint4 ALv = __ldcg((const uint4*)(hfL + (ks * 32 + lane) * 4));
            unsigned aH[4] = {AHv.x, AHv.y, AHv.z, AHv.w};
            unsigned aL[4] = {ALv.x, ALv.y, ALv.z, ALv.w};
#pragma unroll
            for (int t = 0; t < 6; ++t) {
                int bi = ((t * 64 + ks) * 32 + lane) * 2;
                uint2 bHv = *(const uint2*)&wsH[bi];
                uint2 bLv = *(const uint2*)&wsL[bi];
                unsigned bH[2] = {bHv.x, bHv.y};
                unsigned bL[2] = {bLv.x, bLv.y};
                mma_bf16(acc[t], aH, bH);
                mma_bf16(acc[t], aL, bH);
                mma_bf16(acc[t], aH, bL);
            }
        }
#pragma unroll
        for (int t = 0; t < 6; ++t)
            *(float4*)&red[((w * 6 + t) * 32 + lane) * 4] =
                make_float4(acc[t][0], acc[t][1], acc[t][2], acc[t][3]);
        __syncthreads();

        // Gates with fused 8-way reduction
        {
            float ghr = br, ghz = bz, ghn = bn2;
#pragma unroll
            for (int ww = 0; ww < 8; ++ww) {
                ghr += red[ww * 768 + foff];
                ghz += red[ww * 768 + 256 + foff];
                ghn += red[ww * 768 + 512 + foff];
            }
            float r = 1.f / (1.f + expf(-(xr + ghr)));
            float z = 1.f / (1.f + expf(-(xz + ghz)));
            float n = tanhf(xn + r * ghn);
            float hnew = (1.f - z) * n + z * hprev;
            hprev = hnew;

            __nv_bfloat16 hhi = __float2bfloat16(hnew);
            float rlo = hnew - __bfloat162float(hhi);
            __nv_bfloat16 hlo = __float2bfloat16(rlo);
            unsigned vh = (unsigned)__bfloat16_as_ushort(hhi);
            unsigned vl = (unsigned)__bfloat16_as_ushort(hlo);
            unsigned ph = __shfl_down_sync(0xffffffffu, vh, 1);
            unsigned pl = __shfl_down_sync(0xffffffffu, vl, 1);
            if ((gu & 1) == 0) {
                unsigned hp = (ph << 16) | vh;
                unsigned lp = (pl << 16) | vl;
                unsigned* oH = HF + ((size_t)(nxt * 2 + dir) * 2 + 0) * 8192;
                unsigned* oL = HF + ((size_t)(nxt * 2 + dir) * 2 + 1) * 8192;
                oH[widx] = hp;
                oL[widx] = lp;
                size_t yi = (size_t)(tt * 16 + gb) * 1024 + dir * 512 + (gj >> 1);
                ((unsigned*)YH)[yi] = hp;
                ((unsigned*)YL)[yi] = lp;
            }
        }

        // Per-direction grid barrier (release/acquire)
        __syncthreads();
        if (tid == 0) {
            red_release_add(bard, 1u);
            unsigned tgt = (unsigned)(s + 1) * 64;
            while (ld_acquire(bard) < tgt) { }
        }
        __syncthreads();
    }
}

// ---------------------------------------------------------------------------
extern "C" void kernel_launch(void* const* d_in, const int* in_sizes, int n_in,
                              void* d_out, int out_size)
{
    const float* inp     = (const float*)d_in[0];
    const float* w_in    = (const float*)d_in[1];
    const float* b_in    = (const float*)d_in[2];
    const float* w_ih_l0 = (const float*)d_in[3];
    const float* w_hh_l0 = (const float*)d_in[4];
    const float* b_ih_l0 = (const float*)d_in[5];
    const float* b_hh_l0 = (const float*)d_in[6];
    const float* w_ih_l1 = (const float*)d_in[7];
    const float* w_hh_l1 = (const float*)d_in[8];
    const float* b_ih_l1 = (const float*)d_in[9];
    const float* b_hh_l1 = (const float*)d_in[10];
    const float* w_out   = (const float*)d_in[11];
    const float* b_out   = (const float*)d_in[12];
    float* out = (float*)d_out;

    float* S = nullptr;
    cudaGetSymbolAddress((void**)&S, g_scratch);
    __nv_bfloat16* BF = nullptr;
    cudaGetSymbolAddress((void**)&BF, g_bf);

    float* GX0  = S + OFF_GX0;
    float* GX1  = S + OFF_GX1;
    float* OUTT = S + OFF_OUTT;
    unsigned* WFH = (unsigned*)(S + OFF_WFH);
    unsigned* WFL = (unsigned*)(S + OFF_WFL);
    unsigned* HF  = (unsigned*)(S + OFF_HF);
    unsigned* BAR = (unsigned*)(S + OFF_BAR);

    cudaFuncSetAttribute(gemm_bf16_split_kernel,
                         cudaFuncAttributeMaxDynamicSharedMemorySize, SMEM_GEMM);
    cudaFuncSetAttribute(gru_layer_tc_kernel,
                         cudaFuncAttributeMaxDynamicSharedMemorySize, REC_SMEM);

    const int M = Tt * Bb;  // 8192
    const int WF_BLKS = (int)(SZ_WFp / 256);
    const size_t WSPLIT_N = SZ_WINe + SZ_WI0e + SZ_WI1e + SZ_WOe;

    // 1) Transpose+split input
    transpose_in_split_kernel<<<dim3(Tt / 32, INP / 32, Bb), dim3(32, 8)>>>(
        inp, BF + BOFF_XH, BF + BOFF_XL);

    // 2) All weight splits
    wsplit_all_kernel<<<(int)((WSPLIT_N + 255) / 256), 256>>>(
        w_in, w_ih_l0, w_ih_l1, w_out, BF);

    // 3) Input projection (bf16 split output)
    gemm_bf16_split_kernel<<<dim3(F / 128, M / 128), 256, SMEM_GEMM>>>(
        BF + BOFF_XH, BF + BOFF_XL, BF + BOFF_WINH, BF + BOFF_WINL, b_in,
        nullptr, BF + BOFF_H0H, BF + BOFF_H0L, M, F, INP);

    // 4) Layer 0 gx (fp32)
    gemm_bf16_split_kernel<<<dim3(6 * F / 128, M / 128), 256, SMEM_GEMM>>>(
        BF + BOFF_H0H, BF + BOFF_H0L, BF + BOFF_WI0H, BF + BOFF_WI0L, b_ih_l0,
        GX0, nullptr, nullptr, M, 6 * F, F);

    // 5) Prepack W_hh layer 0 (+zero HF/BAR)
    prepack_whh_kernel<<<WF_BLKS, 256>>>(w_hh_l0, WFH, WFL, HF, BAR);

    // 6) Layer 0 recurrence  <-- ncu -s 5 captures this launch
    gru_layer_tc_kernel<<<NBLK, 256, REC_SMEM>>>(
        WFH, WFL, b_hh_l0, GX0, BF + BOFF_Y0H, BF + BOFF_Y0L, HF, BAR);

    // 7) Layer 1 gx
    gemm_bf16_split_kernel<<<dim3(6 * F / 128, M / 128), 256, SMEM_GEMM>>>(
        BF + BOFF_Y0H, BF + BOFF_Y0L, BF + BOFF_WI1H, BF + BOFF_WI1L, b_ih_l1,
        GX1, nullptr, nullptr, M, 6 * F, 2 * F);

    // 8) Prepack W_hh layer 1 (+zero HF/BAR)
    prepack_whh_kernel<<<WF_BLKS, 256>>>(w_hh_l1, WFH, WFL, HF, BAR);

    // 9) Layer 1 recurrence
    gru_layer_tc_kernel<<<NBLK, 256, REC_SMEM>>>(
        WFH, WFL, b_hh_l1, GX1, BF + BOFF_Y1H, BF + BOFF_Y1L, HF, BAR);

    // 10) Output projection (fp32)
    gemm_bf16_split_kernel<<<dim3(OUTD / 128, M / 128), 256, SMEM_GEMM>>>(
        BF + BOFF_Y1H, BF + BOFF_Y1L, BF + BOFF_WOH, BF + BOFF_WOL, b_out,
        OUTT, nullptr, nullptr, M, OUTD, 2 * F);

    // 11) Final transpose
    transpose_out_kernel<<<dim3(Tt / 32, OUTD / 32, Bb), dim3(32, 8)>>>(OUTT, out);
}

// round 6
// speedup vs baseline: 4.2431x; 1.1375x over previous
#include <cuda_runtime.h>
#include <cuda_bf16.h>
#include <cstddef>

// Problem constants
constexpr int Tt   = 512;
constexpr int Bb   = 16;
constexpr int F    = 1024;
constexpr int INP  = 2048;
constexpr int OUTD = 1024;

constexpr int NBLK = 128;

// ---------------------------------------------------------------------------
// Float/u32 scratch
// ---------------------------------------------------------------------------
constexpr size_t OFF_GX0  = 0;
constexpr size_t SZ_GX    = (size_t)Tt * Bb * 6 * F;
constexpr size_t OFF_GX1  = OFF_GX0 + SZ_GX;
constexpr size_t OFF_OUTT = OFF_GX1 + SZ_GX;
constexpr size_t SZ_OUTT  = (size_t)Tt * Bb * OUTD;
// W_hh fragment planes per layer (u32): [dir2][blk64][tile6][kstep64][lane32][reg2]
constexpr size_t SZ_WFp   = (size_t)2 * 64 * 6 * 64 * 32 * 2;   // 3145728
constexpr size_t OFF_WFH0 = OFF_OUTT + SZ_OUTT;
constexpr size_t OFF_WFL0 = OFF_WFH0 + SZ_WFp;
constexpr size_t OFF_WFH1 = OFF_WFL0 + SZ_WFp;
constexpr size_t OFF_WFL1 = OFF_WFH1 + SZ_WFp;
// h fragments per layer: [parity2][dir2][plane2][kstep64][lane32][reg4] u32
constexpr size_t SZ_HF    = (size_t)2 * 2 * 2 * 64 * 32 * 4;    // 65536
constexpr size_t OFF_HF0  = OFF_WFL1 + SZ_WFp;
constexpr size_t OFF_HF1  = OFF_HF0 + SZ_HF;
constexpr size_t OFF_BAR0 = OFF_HF1 + SZ_HF;    // 16 u32
constexpr size_t OFF_BAR1 = OFF_BAR0 + 16;
constexpr size_t SCRATCH_TOTAL = OFF_BAR1 + 16;

__device__ float g_scratch[SCRATCH_TOTAL];

// ---------------------------------------------------------------------------
// bf16 scratch (hi/lo planes)
// ---------------------------------------------------------------------------
constexpr size_t SZ_Xe   = (size_t)Tt * Bb * INP;
constexpr size_t SZ_H0e  = (size_t)Tt * Bb * F;
constexpr size_t SZ_Ye   = (size_t)Tt * Bb * 2 * F;
constexpr size_t SZ_WINe = (size_t)F * INP;
constexpr size_t SZ_WI0e = (size_t)6 * F * F;
constexpr size_t SZ_WI1e = (size_t)6 * F * 2 * F;
constexpr size_t SZ_WOe  = (size_t)OUTD * 2 * F;

constexpr size_t BOFF_XH  = 0;
constexpr size_t BOFF_XL  = BOFF_XH  + SZ_Xe;
constexpr size_t BOFF_H0H = BOFF_XL  + SZ_Xe;
constexpr size_t BOFF_H0L = BOFF_H0H + SZ_H0e;
constexpr size_t BOFF_Y0H = BOFF_H0L + SZ_H0e;
constexpr size_t BOFF_Y0L = BOFF_Y0H + SZ_Ye;
constexpr size_t BOFF_Y1H = BOFF_Y0L + SZ_Ye;
constexpr size_t BOFF_Y1L = BOFF_Y1H + SZ_Ye;
constexpr size_t BOFF_WINH= BOFF_Y1L + SZ_Ye;
constexpr size_t BOFF_WINL= BOFF_WINH+ SZ_WINe;
constexpr size_t BOFF_WI0H= BOFF_WINL+ SZ_WINe;
constexpr size_t BOFF_WI0L= BOFF_WI0H+ SZ_WI0e;
constexpr size_t BOFF_WI1H= BOFF_WI0L+ SZ_WI0e;
constexpr size_t BOFF_WI1L= BOFF_WI1H+ SZ_WI1e;
constexpr size_t BOFF_WOH = BOFF_WI1L+ SZ_WI1e;
constexpr size_t BOFF_WOL = BOFF_WOH + SZ_WOe;
constexpr size_t BF_TOTAL = BOFF_WOL + SZ_WOe;

__device__ __nv_bfloat16 g_bf[BF_TOTAL];

// ---------------------------------------------------------------------------
__device__ __forceinline__ void split_store(float v, __nv_bfloat16* h, __nv_bfloat16* l) {
    __nv_bfloat16 hi = __float2bfloat16(v);
    *h = hi;
    *l = __float2bfloat16(v - __bfloat162float(hi));
}

// ---------------------------------------------------------------------------
// Mega-prep kernel: weight splits + W_hh prepacks (both layers) + HF/BAR zero
// + input transpose/split. One launch -> recurrence lands at launch #4.
// ---------------------------------------------------------------------------
constexpr size_t WSPLIT_N  = SZ_WINe + SZ_WI0e + SZ_WI1e + SZ_WOe;   // 23068672
constexpr int NB_WSPLIT  = (int)(WSPLIT_N / 256);                    // 90112
constexpr int NB_PREPACK = (int)(SZ_WFp / 256);                      // 12288
constexpr int NB_ZERO    = 513;
constexpr int NB_TRANS   = (Tt / 32) * (INP / 32) * Bb;              // 16384
constexpr int NB_PREP    = NB_WSPLIT + 2 * NB_PREPACK + NB_ZERO + NB_TRANS;

__device__ __forceinline__ void prepack_one(const float* __restrict__ whh,
                                            unsigned* __restrict__ wfh,
                                            unsigned* __restrict__ wfl, size_t i)
{
    size_t i2 = i;
    int r   = (int)(i2 & 1);  i2 >>= 1;
    int l   = (int)(i2 & 31); i2 >>= 5;
    int ks  = (int)(i2 & 63); i2 >>= 6;
    int t   = (int)(i2 % 6);  i2 /= 6;
    int blk = (int)(i2 & 63); i2 >>= 6;
    int d   = (int)i2;
    int g = t >> 1, half = t & 1;
    int row = g * 1024 + blk * 16 + half * 8 + (l >> 2);
    int k   = ks * 16 + r * 8 + (l & 3) * 2;
    float w0 = whh[((size_t)d * 3072 + row) * 1024 + k];
    float w1 = whh[((size_t)d * 3072 + row) * 1024 + k + 1];
    __nv_bfloat16 h0 = __float2bfloat16(w0);
    __nv_bfloat16 h1 = __float2bfloat16(w1);
    __nv_bfloat16 l0 = __float2bfloat16(w0 - __bfloat162float(h0));
    __nv_bfloat16 l1 = __float2bfloat16(w1 - __bfloat162float(h1));
    wfh[i] = ((unsigned)__bfloat16_as_ushort(h1) << 16) | (unsigned)__bfloat16_as_ushort(h0);
    wfl[i] = ((unsigned)__bfloat16_as_ushort(l1) << 16) | (unsigned)__bfloat16_as_ushort(l0);
}

__global__ void __launch_bounds__(256) prep_kernel(
    const float* __restrict__ inp,
    const float* __restrict__ w_in, const float* __restrict__ w_ih_l0,
    const float* __restrict__ w_ih_l1, const float* __restrict__ w_out,
    const float* __restrict__ whh0, const float* __restrict__ whh1,
    __nv_bfloat16* __restrict__ BF,
    unsigned* __restrict__ WFH0, unsigned* __restrict__ WFL0,
    unsigned* __restrict__ WFH1, unsigned* __restrict__ WFL1,
    unsigned* __restrict__ HF0, unsigned* __restrict__ HF1,
    unsigned* __restrict__ BAR0, unsigned* __restrict__ BAR1)
{
    __shared__ float tile[32][33];
    int bid = blockIdx.x;
    int tid = threadIdx.x;

    if (bid < NB_WSPLIT) {
        size_t i = (size_t)bid * 256 + tid;
        const float* src; size_t hoff, loff, idx;
        if (i < SZ_WINe) {
            src = w_in; idx = i; hoff = BOFF_WINH + i; loff = BOFF_WINL + i;
        } else if (i < SZ_WINe + SZ_WI0e) {
            idx = i - SZ_WINe; src = w_ih_l0; hoff = BOFF_WI0H + idx; loff = BOFF_WI0L + idx;
        } else if (i < SZ_WINe + SZ_WI0e + SZ_WI1e) {
            idx = i - SZ_WINe - SZ_WI0e; src = w_ih_l1; hoff = BOFF_WI1H + idx; loff = BOFF_WI1L + idx;
        } else {
            idx = i - SZ_WINe - SZ_WI0e - SZ_WI1e; src = w_out; hoff = BOFF_WOH + idx; loff = BOFF_WOL + idx;
        }
        split_store(src[idx], BF + hoff, BF + loff);
        return;
    }
    bid -= NB_WSPLIT;

    if (bid < NB_PREPACK) {
        prepack_one(whh0, WFH0, WFL0, (size_t)bid * 256 + tid);
        return;
    }
    bid -= NB_PREPACK;

    if (bid < NB_PREPACK) {
        prepack_one(whh1, WFH1, WFL1, (size_t)bid * 256 + tid);
        return;
    }
    bid -= NB_PREPACK;

    if (bid < NB_ZERO) {
        size_t i = (size_t)bid * 256 + tid;
        if (i < SZ_HF) HF0[i] = 0;
        else if (i < 2 * SZ_HF) HF1[i - SZ_HF] = 0;
        else if (i < 2 * SZ_HF + 16) BAR0[i - 2 * SZ_HF] = 0;
        else if (i < 2 * SZ_HF + 32) BAR1[i - 2 * SZ_HF - 16] = 0;
        return;
    }
    bid -= NB_ZERO;

    // Input transpose + split: inp [B][INP][T] -> XH/XL [T*B][INP]
    {
        int b   = bid >> 10;
        int rem = bid & 1023;
        int i0  = (rem >> 4) * 32;
        int t0  = (rem & 15) * 32;
        int tx = tid & 31, ty = tid >> 5;
#pragma unroll
        for (int j = 0; j < 32; j += 8)
            tile[ty + j][tx] = inp[((size_t)b * INP + (i0 + ty + j)) * Tt + t0 + tx];
        __syncthreads();
        __nv_bfloat16* XH = BF + BOFF_XH;
        __nv_bfloat16* XL = BF + BOFF_XL;
#pragma unroll
        for (int j = 0; j < 32; j += 8) {
            size_t o = ((size_t)(t0 + ty + j) * Bb + b) * INP + i0 + tx;
            split_store(tile[tx][ty + j], XH + o, XL + o);
        }
    }
}

__global__ void transpose_out_kernel(const float* __restrict__ in, float* __restrict__ out) {
    __shared__ float tile[32][33];
    int b  = blockIdx.z;
    int t0 = blockIdx.x * 32;
    int o0 = blockIdx.y * 32;
    int tx = threadIdx.x, ty = threadIdx.y;
#pragma unroll
    for (int j = 0; j < 32; j += 8)
        tile[ty + j][tx] = in[((size_t)(t0 + ty + j) * Bb + b) * OUTD + o0 + tx];
    __syncthreads();
#pragma unroll
    for (int j = 0; j < 32; j += 8)
        out[((size_t)b * OUTD + (o0 + ty + j)) * Tt + t0 + tx] = tile[tx][ty + j];
}

// ---------------------------------------------------------------------------
// Tensor-core split-bf16 GEMM; 2 CTAs/SM (stride 40, 80KB smem, 128 regs)
// ---------------------------------------------------------------------------
constexpr int TW  = 40;            // bf16 per smem row; conflict-free for ldsm
constexpr int PL  = 128 * TW;
constexpr int GBUF = 4 * PL;
constexpr int SMEM_GEMM = 2 * GBUF * (int)sizeof(__nv_bfloat16);  // 81920

__device__ __forceinline__ void cpa16(void* sdst, const void* gsrc) {
    unsigned s = (unsigned)__cvta_generic_to_shared(sdst);
    asm volatile("cp.async.cg.shared.global [%0], [%1], 16;\n" :: "r"(s), "l"(gsrc));
}
__device__ __forceinline__ void cpa_commit() {
    asm volatile("cp.async.commit_group;\n" ::);
}
__device__ __forceinline__ void cpa_wait0() {
    asm volatile("cp.async.wait_group 0;\n" ::);
}
__device__ __forceinline__ void mma_bf16(float* c, const unsigned* a, const unsigned* b) {
    asm volatile(
        "mma.sync.aligned.m16n8k16.row.col.f32.bf16.bf16.f32 "
        "{%0,%1,%2,%3},{%4,%5,%6,%7},{%8,%9},{%0,%1,%2,%3};\n"
        : "+f"(c[0]), "+f"(c[1]), "+f"(c[2]), "+f"(c[3])
        : "r"(a[0]), "r"(a[1]), "r"(a[2]), "r"(a[3]), "r"(b[0]), "r"(b[1]));
}
__device__ __forceinline__ void ldsm4(unsigned* r, const __nv_bfloat16* p) {
    unsigned a = (unsigned)__cvta_generic_to_shared(p);
    asm volatile("ldmatrix.sync.aligned.m8n8.x4.shared.b16 {%0,%1,%2,%3},[%4];\n"
        : "=r"(r[0]), "=r"(r[1]), "=r"(r[2]), "=r"(r[3]) : "r"(a));
}
__device__ __forceinline__ void ldsm2(unsigned* r, const __nv_bfloat16* p) {
    unsigned a = (unsigned)__cvta_generic_to_shared(p);
    asm volatile("ldmatrix.sync.aligned.m8n8.x2.shared.b16 {%0,%1},[%2];\n"
        : "=r"(r[0]), "=r"(r[1]) : "r"(a));
}

__global__ void __launch_bounds__(256, 2) gemm_bf16_split_kernel(
    const __nv_bfloat16* __restrict__ Ah, const __nv_bfloat16* __restrict__ Al,
    const __nv_bfloat16* __restrict__ Wh, const __nv_bfloat16* __restrict__ Wl,
    const float* __restrict__ bias,
    float* __restrict__ C,
    __nv_bfloat16* __restrict__ CH, __nv_bfloat16* __restrict__ CL,
    int M, int N, int K)
{
    extern __shared__ __nv_bfloat16 smx[];
    const int tid = threadIdx.x;
    const int bm = blockIdx.y * 128, bn = blockIdx.x * 128;
    const int lane = tid & 31, wid = tid >> 5;
    const int wm = wid & 1, wn = wid >> 1;
    const int g = lane >> 2, t = lane & 3;

    float acc[4][4][4];
#pragma unroll
    for (int i = 0; i < 4; ++i)
#pragma unroll
        for (int j = 0; j < 4; ++j)
#pragma unroll
            for (int q = 0; q < 4; ++q) acc[i][j][q] = 0.f;

    const int r0 = tid >> 2;
    const int c0 = (tid & 3) * 8;
    const int nk = K / 32;

    const int aOff = (wm * 64 + (lane & 7) + ((lane >> 3) & 1) * 8) * TW + (lane >> 4) * 8;
    const int lb = lane & 15;
    const int bOff = (wn * 32 + (lb & 7)) * TW + ((lb >> 3) & 1) * 8;

    {
        __nv_bfloat16* s = smx;
#pragma unroll
        for (int p = 0; p < 2; ++p) {
            int row = r0 + p * 64;
            size_t ga = (size_t)(bm + row) * K + c0;
            size_t gw = (size_t)(bn + row) * K + c0;
            int so = row * TW + c0;
            cpa16(s + 0 * PL + so, Ah + ga);
            cpa16(s + 1 * PL + so, Al + ga);
            cpa16(s + 2 * PL + so, Wh + gw);
            cpa16(s + 3 * PL + so, Wl + gw);
        }
        cpa_commit();
    }

    for (int kt = 0; kt < nk; ++kt) {
        cpa_wait0();
        __syncthreads();

        if (kt + 1 < nk) {
            __nv_bfloat16* s = smx + ((kt + 1) & 1) * GBUF;
            int k0 = (kt + 1) * 32;
#pragma unroll
            for (int p = 0; p < 2; ++p) {
                int row = r0 + p * 64;
                size_t ga = (size_t)(bm + row) * K + k0 + c0;
                size_t gw = (size_t)(bn + row) * K + k0 + c0;
                int so = row * TW + c0;
                cpa16(s + 0 * PL + so, Ah + ga);
                cpa16(s + 1 * PL + so, Al + ga);
                cpa16(s + 2 * PL + so, Wh + gw);
                cpa16(s + 3 * PL + so, Wl + gw);
            }
            cpa_commit();
        }

        const __nv_bfloat16* sb = smx + (kt & 1) * GBUF;

#pragma unroll
        for (int ks = 0; ks < 2; ++ks) {
            unsigned aH[4][4], aL[4][4], bH[4][2], bL[4][2];
#pragma unroll
            for (int i = 0; i < 4; ++i) {
                int off = aOff + i * 16 * TW + ks * 16;
                ldsm4(aH[i], sb + 0 * PL + off);
                ldsm4(aL[i], sb + 1 * PL + off);
            }
#pragma unroll
            for (int j = 0; j < 4; ++j) {
                int off = bOff + j * 8 * TW + ks * 16;
                ldsm2(bH[j], sb + 2 * PL + off);
                ldsm2(bL[j], sb + 3 * PL + off);
            }
#pragma unroll
            for (int i = 0; i < 4; ++i)
#pragma unroll
                for (int j = 0; j < 4; ++j) {
                    mma_bf16(acc[i][j], aH[i], bH[j]);
                    mma_bf16(acc[i][j], aH[i], bL[j]);
                    mma_bf16(acc[i][j], aL[i], bH[j]);
                }
        }
    }

#pragma unroll
    for (int i = 0; i < 4; ++i) {
        int row0 = bm + wm * 64 + i * 16 + g;
#pragma unroll
        for (int j = 0; j < 4; ++j) {
            int col = bn + wn * 32 + j * 8 + t * 2;
            float b0 = bias[col], b1 = bias[col + 1];
            float v00 = acc[i][j][0] + b0, v01 = acc[i][j][1] + b1;
            float v10 = acc[i][j][2] + b0, v11 = acc[i][j][3] + b1;
            if (CH) {
                size_t p0 = (size_t)row0 * N + col;
                size_t p1 = (size_t)(row0 + 8) * N + col;
                __nv_bfloat16 h00 = __float2bfloat16(v00), h01 = __float2bfloat16(v01);
                __nv_bfloat16 h10 = __float2bfloat16(v10), h11 = __float2bfloat16(v11);
                *(__nv_bfloat162*)(CH + p0) = __nv_bfloat162(h00, h01);
                *(__nv_bfloat162*)(CH + p1) = __nv_bfloat162(h10, h11);
                *(__nv_bfloat162*)(CL + p0) = __nv_bfloat162(
                    __float2bfloat16(v00 - __bfloat162float(h00)),
                    __float2bfloat16(v01 - __bfloat162float(h01)));
                *(__nv_bfloat162*)(CL + p1) = __nv_bfloat162(
                    __float2bfloat16(v10 - __bfloat162float(h10)),
                    __float2bfloat16(v11 - __bfloat162float(h11)));
            } else {
                *(float2*)(C + (size_t)row0 * N + col) = make_float2(v00, v01);
                *(float2*)(C + (size_t)(row0 + 8) * N + col) = make_float2(v10, v11);
            }
        }
    }
}

// ---------------------------------------------------------------------------
// Persistent tensor-core bidirectional GRU layer.
// W-hi fragments in registers (loaded once), W-lo in smem.
// ---------------------------------------------------------------------------
constexpr int WS_U32 = 6 * 64 * 32 * 2;
constexpr int REC_SMEM = (2 * WS_U32) * 4 + (8 * 768) * 4;

__device__ __forceinline__ unsigned ld_acquire(const unsigned* p) {
    unsigned v;
    asm volatile("ld.global.acquire.gpu.u32 %0, [%1];" : "=r"(v) : "l"(p) : "memory");
    return v;
}
__device__ __forceinline__ void red_release_add(unsigned* p, unsigned v) {
    asm volatile("red.release.gpu.global.add.u32 [%0], %1;" :: "l"(p), "r"(v) : "memory");
}

__global__ void __launch_bounds__(256, 1) gru_layer_tc_kernel(
    const unsigned* __restrict__ WFH, const unsigned* __restrict__ WFL,
    const float* __restrict__ bhh,
    const float* __restrict__ gx,
    __nv_bfloat16* __restrict__ YH, __nv_bfloat16* __restrict__ YL,
    unsigned* __restrict__ HF,
    unsigned* __restrict__ bar)
{
    extern __shared__ unsigned smu[];
    unsigned* wsH = smu;
    unsigned* wsL = smu + WS_U32;
    float* red = (float*)(smu + 2 * WS_U32);

    const int tid = threadIdx.x;
    const int dir = blockIdx.x >> 6;
    const int blk = blockIdx.x & 63;
    const int u0  = blk * 16;
    const int lane = tid & 31, w = tid >> 5;
    unsigned* bard = bar + dir * 8;

    {
        const uint4* srcH = (const uint4*)(WFH + (size_t)(dir * 64 + blk) * WS_U32);
        const uint4* srcL = (const uint4*)(WFL + (size_t)(dir * 64 + blk) * WS_U32);
        uint4* dH = (uint4*)wsH;
        uint4* dL = (uint4*)wsL;
        for (int i = tid; i < WS_U32 / 4; i += 256) { dH[i] = srcH[i]; dL[i] = srcL[i]; }
    }

    const int gb = tid >> 4;
    const int gu = tid & 15;
    const int gj = u0 + gu;
    const float br  = bhh[dir * 3072 + gj];
    const float bz  = bhh[dir * 3072 + 1024 + gj];
    const float bn2 = bhh[dir * 3072 + 2048 + gj];
    float hprev = 0.f;

    const int ksb   = u0 >> 4;
    const int wlane = ((gb & 7) << 2) + ((gu & 7) >> 1);
    const int wreg  = ((gu >= 8) ? 2 : 0) + ((gb >= 8) ? 1 : 0);
    const int widx  = (ksb * 32 + wlane) * 4 + wreg;

    const int fhalf = (gu >= 8) ? 1 : 0;
    const int foff  = fhalf * 128 + wlane * 4 + (gu & 1) + ((gb >= 8) ? 2 : 0);

    __syncthreads();

    // Park this warp's W-hi fragments in registers for all 512 steps
    unsigned bHreg[8][6][2];
#pragma unroll
    for (int kk = 0; kk < 8; ++kk) {
        int ks = w * 8 + kk;
#pragma unroll
        for (int t = 0; t < 6; ++t) {
            uint2 v = *(const uint2*)&wsH[((t * 64 + ks) * 32 + lane) * 2];
            bHreg[kk][t][0] = v.x;
            bHreg[kk][t][1] = v.y;
        }
    }

    for (int s = 0; s < Tt; ++s) {
        const int cur = s & 1, nxt = cur ^ 1;
        const int tt  = dir ? (Tt - 1 - s) : s;

        const float* gxp = gx + (size_t)(tt * 16 + gb) * 6144 + dir * 3072;
        float xr = __ldg(gxp + gj);
        float xz = __ldg(gxp + 1024 + gj);
        float xn = __ldg(gxp + 2048 + gj);

        float acc[6][4];
#pragma unroll
        for (int t = 0; t < 6; ++t)
#pragma unroll
            for (int q = 0; q < 4; ++q) acc[t][q] = 0.f;

        const unsigned* hfH = HF + ((size_t)(cur * 2 + dir) * 2 + 0) * 8192;
        const unsigned* hfL = HF + ((size_t)(cur * 2 + dir) * 2 + 1) * 8192;

#pragma unroll
        for (int kk = 0; kk < 8; ++kk) {
            int ks = w * 8 + kk;
            uint4 AHv = __ldcg((const uint4*)(hfH + (ks * 32 + lane) * 4));
            uint4 ALv = __ldcg((const uint4*)(hfL + (ks * 32 + lane) * 4));
            unsigned aH[4] = {AHv.x, AHv.y, AHv.z, AHv.w};
            unsigned aL[4] = {ALv.x, ALv.y, ALv.z, ALv.w};
#pragma unroll
            for (int t = 0; t < 6; ++t) {
                uint2 bLv = *(const uint2*)&wsL[((t * 64 + ks) * 32 + lane) * 2];
                unsigned bL[2] = {bLv.x, bLv.y};
                mma_bf16(acc[t], aH, bHreg[kk][t]);
                mma_bf16(acc[t], aL, bHreg[kk][t]);
                mma_bf16(acc[t], aH, bL);
            }
        }
#pragma unroll
        for (int t = 0; t < 6; ++t)
            *(float4*)&red[((w * 6 + t) * 32 + lane) * 4] =
                make_float4(acc[t][0], acc[t][1], acc[t][2], acc[t][3]);
        __syncthreads();

        {
            float ghr = br, ghz = bz, ghn = bn2;
#pragma unroll
            for (int ww = 0; ww < 8; ++ww) {
                ghr += red[ww * 768 + foff];
                ghz += red[ww * 768 + 256 + foff];
                ghn += red[ww * 768 + 512 + foff];
            }
            float r = 1.f / (1.f + expf(-(xr + ghr)));
            float z = 1.f / (1.f + expf(-(xz + ghz)));
            float n = tanhf(xn + r * ghn);
            float hnew = (1.f - z) * n + z * hprev;
            hprev = hnew;

            __nv_bfloat16 hhi = __float2bfloat16(hnew);
            float rlo = hnew - __bfloat162float(hhi);
            __nv_bfloat16 hlo = __float2bfloat16(rlo);
            unsigned vh = (unsigned)__bfloat16_as_ushort(hhi);
            unsigned vl = (unsigned)__bfloat16_as_ushort(hlo);
            unsigned ph = __shfl_down_sync(0xffffffffu, vh, 1);
            unsigned pl = __shfl_down_sync(0xffffffffu, vl, 1);
            if ((gu & 1) == 0) {
                unsigned hp = (ph << 16) | vh;
                unsigned lp = (pl << 16) | vl;
                unsigned* oH = HF + ((size_t)(nxt * 2 + dir) * 2 + 0) * 8192;
                unsigned* oL = HF + ((size_t)(nxt * 2 + dir) * 2 + 1) * 8192;
                oH[widx] = hp;
                oL[widx] = lp;
                size_t yi = (size_t)(tt * 16 + gb) * 1024 + dir * 512 + (gj >> 1);
                ((unsigned*)YH)[yi] = hp;
                ((unsigned*)YL)[yi] = lp;
            }
        }

        __syncthreads();
        if (tid == 0) {
            red_release_add(bard, 1u);
            unsigned tgt = (unsigned)(s + 1) * 64;
            while (ld_acquire(bard) < tgt) { }
        }
        __syncthreads();
    }
}

// ---------------------------------------------------------------------------
extern "C" void kernel_launch(void* const* d_in, const int* in_sizes, int n_in,
                              void* d_out, int out_size)
{
    const float* inp     = (const float*)d_in[0];
    const float* w_in    = (const float*)d_in[1];
    const float* b_in    = (const float*)d_in[2];
    const float* w_ih_l0 = (const float*)d_in[3];
    const float* w_hh_l0 = (const float*)d_in[4];
    const float* b_ih_l0 = (const float*)d_in[5];
    const float* b_hh_l0 = (const float*)d_in[6];
    const float* w_ih_l1 = (const float*)d_in[7];
    const float* w_hh_l1 = (const float*)d_in[8];
    const float* b_ih_l1 = (const float*)d_in[9];
    const float* b_hh_l1 = (const float*)d_in[10];
    const float* w_out   = (const float*)d_in[11];
    const float* b_out   = (const float*)d_in[12];
    float* out = (float*)d_out;

    float* S = nullptr;
    cudaGetSymbolAddress((void**)&S, g_scratch);
    __nv_bfloat16* BF = nullptr;
    cudaGetSymbolAddress((void**)&BF, g_bf);

    float* GX0  = S + OFF_GX0;
    float* GX1  = S + OFF_GX1;
    float* OUTT = S + OFF_OUTT;
    unsigned* WFH0 = (unsigned*)(S + OFF_WFH0);
    unsigned* WFL0 = (unsigned*)(S + OFF_WFL0);
    unsigned* WFH1 = (unsigned*)(S + OFF_WFH1);
    unsigned* WFL1 = (unsigned*)(S + OFF_WFL1);
    unsigned* HF0  = (unsigned*)(S + OFF_HF0);
    unsigned* HF1  = (unsigned*)(S + OFF_HF1);
    unsigned* BAR0 = (unsigned*)(S + OFF_BAR0);
    unsigned* BAR1 = (unsigned*)(S + OFF_BAR1);

    cudaFuncSetAttribute(gemm_bf16_split_kernel,
                         cudaFuncAttributeMaxDynamicSharedMemorySize, SMEM_GEMM);
    cudaFuncSetAttribute(gru_layer_tc_kernel,
                         cudaFuncAttributeMaxDynamicSharedMemorySize, REC_SMEM);

    const int M = Tt * Bb;  // 8192

    // 1) Mega-prep: wsplits + prepacks + zeroing + input transpose/split
    prep_kernel<<<NB_PREP, 256>>>(inp, w_in, w_ih_l0, w_ih_l1, w_out,
                                  w_hh_l0, w_hh_l1, BF,
                                  WFH0, WFL0, WFH1, WFL1, HF0, HF1, BAR0, BAR1);

    // 2) Input projection (bf16 split output)
    gemm_bf16_split_kernel<<<dim3(F / 128, M / 128), 256, SMEM_GEMM>>>(
        BF + BOFF_XH, BF + BOFF_XL, BF + BOFF_WINH, BF + BOFF_WINL, b_in,
        nullptr, BF + BOFF_H0H, BF + BOFF_H0L, M, F, INP);

    // 3) Layer 0 gx
    gemm_bf16_split_kernel<<<dim3(6 * F / 128, M / 128), 256, SMEM_GEMM>>>(
        BF + BOFF_H0H, BF + BOFF_H0L, BF + BOFF_WI0H, BF + BOFF_WI0L, b_ih_l0,
        GX0, nullptr, nullptr, M, 6 * F, F);

    // 4) Layer 0 recurrence  <-- ncu capture slot
    gru_layer_tc_kernel<<<NBLK, 256, REC_SMEM>>>(
        WFH0, WFL0, b_hh_l0, GX0, BF + BOFF_Y0H, BF + BOFF_Y0L, HF0, BAR0);

    // 5) Layer 1 gx
    gemm_bf16_split_kernel<<<dim3(6 * F / 128, M / 128), 256, SMEM_GEMM>>>(
        BF + BOFF_Y0H, BF + BOFF_Y0L, BF + BOFF_WI1H, BF + BOFF_WI1L, b_ih_l1,
        GX1, nullptr, nullptr, M, 6 * F, 2 * F);

    // 6) Layer 1 recurrence
    gru_layer_tc_kernel<<<NBLK, 256, REC_SMEM>>>(
        WFH1, WFL1, b_hh_l1, GX1, BF + BOFF_Y1H, BF + BOFF_Y1L, HF1, BAR1);

    // 7) Output projection
    gemm_bf16_split_kernel<<<dim3(OUTD / 128, M / 128), 256, SMEM_GEMM>>>(
        BF + BOFF_Y1H, BF + BOFF_Y1L, BF + BOFF_WOH, BF + BOFF_WOL, b_out,
        OUTT, nullptr, nullptr, M, OUTD, 2 * F);

    // 8) Final transpose
    transpose_out_kernel<<<dim3(Tt / 32, OUTD / 32, Bb), dim3(32, 8)>>>(OUTT, out);
}

// round 7
// speedup vs baseline: 4.3528x; 1.0259x over previous
#include <cuda_runtime.h>
#include <cuda_bf16.h>
#include <cstddef>

// Problem constants
constexpr int Tt   = 512;
constexpr int Bb   = 16;
constexpr int F    = 1024;
constexpr int INP  = 2048;
constexpr int OUTD = 1024;

// ---------------------------------------------------------------------------
// Float/u32 scratch
// ---------------------------------------------------------------------------
constexpr size_t OFF_GX0  = 0;
constexpr size_t SZ_GX    = (size_t)Tt * Bb * 6 * F;
constexpr size_t OFF_GX1  = OFF_GX0 + SZ_GX;
constexpr size_t OFF_OUTT = OFF_GX1 + SZ_GX;
constexpr size_t SZ_OUTT  = (size_t)Tt * Bb * OUTD;
// W_hh fragment planes per layer (u32): [dir2][blk16_64][tile6][kstep64][lane32][reg2]
constexpr size_t SZ_WFp   = (size_t)2 * 64 * 6 * 64 * 32 * 2;   // 3145728
constexpr size_t OFF_WFH0 = OFF_OUTT + SZ_OUTT;
constexpr size_t OFF_WFL0 = OFF_WFH0 + SZ_WFp;
constexpr size_t OFF_WFH1 = OFF_WFL0 + SZ_WFp;
constexpr size_t OFF_WFL1 = OFF_WFH1 + SZ_WFp;
// h fragments per layer: [parity2][dir2][plane2][kstep64][lane32][reg4] u32
constexpr size_t SZ_HF    = (size_t)2 * 2 * 2 * 64 * 32 * 4;    // 65536
constexpr size_t OFF_HF0  = OFF_WFL1 + SZ_WFp;
constexpr size_t OFF_HF1  = OFF_HF0 + SZ_HF;
constexpr size_t OFF_BAR0 = OFF_HF1 + SZ_HF;    // 64 u32 (2 dirs, 128B apart)
constexpr size_t OFF_BAR1 = OFF_BAR0 + 64;
constexpr size_t SCRATCH_TOTAL = OFF_BAR1 + 64;

__device__ float g_scratch[SCRATCH_TOTAL];

// ---------------------------------------------------------------------------
// bf16 scratch (hi/lo planes)
// ---------------------------------------------------------------------------
constexpr size_t SZ_Xe   = (size_t)Tt * Bb * INP;
constexpr size_t SZ_H0e  = (size_t)Tt * Bb * F;
constexpr size_t SZ_Ye   = (size_t)Tt * Bb * 2 * F;
constexpr size_t SZ_WINe = (size_t)F * INP;
constexpr size_t SZ_WI0e = (size_t)6 * F * F;
constexpr size_t SZ_WI1e = (size_t)6 * F * 2 * F;
constexpr size_t SZ_WOe  = (size_t)OUTD * 2 * F;

constexpr size_t BOFF_XH  = 0;
constexpr size_t BOFF_XL  = BOFF_XH  + SZ_Xe;
constexpr size_t BOFF_H0H = BOFF_XL  + SZ_Xe;
constexpr size_t BOFF_H0L = BOFF_H0H + SZ_H0e;
constexpr size_t BOFF_Y0H = BOFF_H0L + SZ_H0e;
constexpr size_t BOFF_Y0L = BOFF_Y0H + SZ_Ye;
constexpr size_t BOFF_Y1H = BOFF_Y0L + SZ_Ye;
constexpr size_t BOFF_Y1L = BOFF_Y1H + SZ_Ye;
constexpr size_t BOFF_WINH= BOFF_Y1L + SZ_Ye;
constexpr size_t BOFF_WINL= BOFF_WINH+ SZ_WINe;
constexpr size_t BOFF_WI0H= BOFF_WINL+ SZ_WINe;
constexpr size_t BOFF_WI0L= BOFF_WI0H+ SZ_WI0e;
constexpr size_t BOFF_WI1H= BOFF_WI0L+ SZ_WI0e;
constexpr size_t BOFF_WI1L= BOFF_WI1H+ SZ_WI1e;
constexpr size_t BOFF_WOH = BOFF_WI1L+ SZ_WI1e;
constexpr size_t BOFF_WOL = BOFF_WOH + SZ_WOe;
constexpr size_t BF_TOTAL = BOFF_WOL + SZ_WOe;

__device__ __nv_bfloat16 g_bf[BF_TOTAL];

// ---------------------------------------------------------------------------
__device__ __forceinline__ void split_store(float v, __nv_bfloat16* h, __nv_bfloat16* l) {
    __nv_bfloat16 hi = __float2bfloat16(v);
    *h = hi;
    *l = __float2bfloat16(v - __bfloat162float(hi));
}

// ---------------------------------------------------------------------------
// Mega-prep kernel: weight splits + W_hh prepacks + HF/BAR zero + input T/split
// ---------------------------------------------------------------------------
constexpr size_t WSPLIT_N  = SZ_WINe + SZ_WI0e + SZ_WI1e + SZ_WOe;
constexpr int NB_WSPLIT  = (int)(WSPLIT_N / 256);
constexpr int NB_PREPACK = (int)(SZ_WFp / 256);
constexpr int NB_ZERO    = 514;
constexpr int NB_TRANS   = (Tt / 32) * (INP / 32) * Bb;
constexpr int NB_PREP    = NB_WSPLIT + 2 * NB_PREPACK + NB_ZERO + NB_TRANS;

__device__ __forceinline__ void prepack_one(const float* __restrict__ whh,
                                            unsigned* __restrict__ wfh,
                                            unsigned* __restrict__ wfl, size_t i)
{
    size_t i2 = i;
    int r   = (int)(i2 & 1);  i2 >>= 1;
    int l   = (int)(i2 & 31); i2 >>= 5;
    int ks  = (int)(i2 & 63); i2 >>= 6;
    int t   = (int)(i2 % 6);  i2 /= 6;
    int blk = (int)(i2 & 63); i2 >>= 6;
    int d   = (int)i2;
    int g = t >> 1, half = t & 1;
    int row = g * 1024 + blk * 16 + half * 8 + (l >> 2);
    int k   = ks * 16 + r * 8 + (l & 3) * 2;
    float w0 = whh[((size_t)d * 3072 + row) * 1024 + k];
    float w1 = whh[((size_t)d * 3072 + row) * 1024 + k + 1];
    __nv_bfloat16 h0 = __float2bfloat16(w0);
    __nv_bfloat16 h1 = __float2bfloat16(w1);
    __nv_bfloat16 l0 = __float2bfloat16(w0 - __bfloat162float(h0));
    __nv_bfloat16 l1 = __float2bfloat16(w1 - __bfloat162float(h1));
    wfh[i] = ((unsigned)__bfloat16_as_ushort(h1) << 16) | (unsigned)__bfloat16_as_ushort(h0);
    wfl[i] = ((unsigned)__bfloat16_as_ushort(l1) << 16) | (unsigned)__bfloat16_as_ushort(l0);
}

__global__ void __launch_bounds__(256) prep_kernel(
    const float* __restrict__ inp,
    const float* __restrict__ w_in, const float* __restrict__ w_ih_l0,
    const float* __restrict__ w_ih_l1, const float* __restrict__ w_out,
    const float* __restrict__ whh0, const float* __restrict__ whh1,
    __nv_bfloat16* __restrict__ BF,
    unsigned* __restrict__ WFH0, unsigned* __restrict__ WFL0,
    unsigned* __restrict__ WFH1, unsigned* __restrict__ WFL1,
    unsigned* __restrict__ HF0, unsigned* __restrict__ HF1,
    unsigned* __restrict__ BAR0, unsigned* __restrict__ BAR1)
{
    __shared__ float tile[32][33];
    int bid = blockIdx.x;
    int tid = threadIdx.x;

    if (bid < NB_WSPLIT) {
        size_t i = (size_t)bid * 256 + tid;
        const float* src; size_t hoff, loff, idx;
        if (i < SZ_WINe) {
            src = w_in; idx = i; hoff = BOFF_WINH + i; loff = BOFF_WINL + i;
        } else if (i < SZ_WINe + SZ_WI0e) {
            idx = i - SZ_WINe; src = w_ih_l0; hoff = BOFF_WI0H + idx; loff = BOFF_WI0L + idx;
        } else if (i < SZ_WINe + SZ_WI0e + SZ_WI1e) {
            idx = i - SZ_WINe - SZ_WI0e; src = w_ih_l1; hoff = BOFF_WI1H + idx; loff = BOFF_WI1L + idx;
        } else {
            idx = i - SZ_WINe - SZ_WI0e - SZ_WI1e; src = w_out; hoff = BOFF_WOH + idx; loff = BOFF_WOL + idx;
        }
        split_store(src[idx], BF + hoff, BF + loff);
        return;
    }
    bid -= NB_WSPLIT;

    if (bid < NB_PREPACK) {
        prepack_one(whh0, WFH0, WFL0, (size_t)bid * 256 + tid);
        return;
    }
    bid -= NB_PREPACK;

    if (bid < NB_PREPACK) {
        prepack_one(whh1, WFH1, WFL1, (size_t)bid * 256 + tid);
        return;
    }
    bid -= NB_PREPACK;

    if (bid < NB_ZERO) {
        size_t i = (size_t)bid * 256 + tid;
        if (i < SZ_HF) HF0[i] = 0;
        else if (i < 2 * SZ_HF) HF1[i - SZ_HF] = 0;
        else if (i < 2 * SZ_HF + 64) BAR0[i - 2 * SZ_HF] = 0;
        else if (i < 2 * SZ_HF + 128) BAR1[i - 2 * SZ_HF - 64] = 0;
        return;
    }
    bid -= NB_ZERO;

    // Input transpose + split
    {
        int b   = bid >> 10;
        int rem = bid & 1023;
        int i0  = (rem >> 4) * 32;
        int t0  = (rem & 15) * 32;
        int tx = tid & 31, ty = tid >> 5;
#pragma unroll
        for (int j = 0; j < 32; j += 8)
            tile[ty + j][tx] = inp[((size_t)b * INP + (i0 + ty + j)) * Tt + t0 + tx];
        __syncthreads();
        __nv_bfloat16* XH = BF + BOFF_XH;
        __nv_bfloat16* XL = BF + BOFF_XL;
#pragma unroll
        for (int j = 0; j < 32; j += 8) {
            size_t o = ((size_t)(t0 + ty + j) * Bb + b) * INP + i0 + tx;
            split_store(tile[tx][ty + j], XH + o, XL + o);
        }
    }
}

__global__ void transpose_out_kernel(const float* __restrict__ in, float* __restrict__ out) {
    __shared__ float tile[32][33];
    int b  = blockIdx.z;
    int t0 = blockIdx.x * 32;
    int o0 = blockIdx.y * 32;
    int tx = threadIdx.x, ty = threadIdx.y;
#pragma unroll
    for (int j = 0; j < 32; j += 8)
        tile[ty + j][tx] = in[((size_t)(t0 + ty + j) * Bb + b) * OUTD + o0 + tx];
    __syncthreads();
#pragma unroll
    for (int j = 0; j < 32; j += 8)
        out[((size_t)b * OUTD + (o0 + ty + j)) * Tt + t0 + tx] = tile[tx][ty + j];
}

// ---------------------------------------------------------------------------
// Tensor-core split-bf16 GEMM; 2 CTAs/SM
// ---------------------------------------------------------------------------
constexpr int TW  = 40;
constexpr int PL  = 128 * TW;
constexpr int GBUF = 4 * PL;
constexpr int SMEM_GEMM = 2 * GBUF * (int)sizeof(__nv_bfloat16);  // 81920

__device__ __forceinline__ void cpa16(void* sdst, const void* gsrc) {
    unsigned s = (unsigned)__cvta_generic_to_shared(sdst);
    asm volatile("cp.async.cg.shared.global [%0], [%1], 16;\n" :: "r"(s), "l"(gsrc));
}
__device__ __forceinline__ void cpa_commit() {
    asm volatile("cp.async.commit_group;\n" ::);
}
__device__ __forceinline__ void cpa_wait0() {
    asm volatile("cp.async.wait_group 0;\n" ::);
}
__device__ __forceinline__ void mma_bf16(float* c, const unsigned* a, const unsigned* b) {
    asm volatile(
        "mma.sync.aligned.m16n8k16.row.col.f32.bf16.bf16.f32 "
        "{%0,%1,%2,%3},{%4,%5,%6,%7},{%8,%9},{%0,%1,%2,%3};\n"
        : "+f"(c[0]), "+f"(c[1]), "+f"(c[2]), "+f"(c[3])
        : "r"(a[0]), "r"(a[1]), "r"(a[2]), "r"(a[3]), "r"(b[0]), "r"(b[1]));
}
__device__ __forceinline__ void ldsm4(unsigned* r, const __nv_bfloat16* p) {
    unsigned a = (unsigned)__cvta_generic_to_shared(p);
    asm volatile("ldmatrix.sync.aligned.m8n8.x4.shared.b16 {%0,%1,%2,%3},[%4];\n"
        : "=r"(r[0]), "=r"(r[1]), "=r"(r[2]), "=r"(r[3]) : "r"(a));
}
__device__ __forceinline__ void ldsm2(unsigned* r, const __nv_bfloat16* p) {
    unsigned a = (unsigned)__cvta_generic_to_shared(p);
    asm volatile("ldmatrix.sync.aligned.m8n8.x2.shared.b16 {%0,%1},[%2];\n"
        : "=r"(r[0]), "=r"(r[1]) : "r"(a));
}

__global__ void __launch_bounds__(256, 2) gemm_bf16_split_kernel(
    const __nv_bfloat16* __restrict__ Ah, const __nv_bfloat16* __restrict__ Al,
    const __nv_bfloat16* __restrict__ Wh, const __nv_bfloat16* __restrict__ Wl,
    const float* __restrict__ bias,
    float* __restrict__ C,
    __nv_bfloat16* __restrict__ CH, __nv_bfloat16* __restrict__ CL,
    int M, int N, int K)
{
    extern __shared__ __nv_bfloat16 smx[];
    const int tid = threadIdx.x;
    const int bm = blockIdx.y * 128, bn = blockIdx.x * 128;
    const int lane = tid & 31, wid = tid >> 5;
    const int wm = wid & 1, wn = wid >> 1;
    const int g = lane >> 2, t = lane & 3;

    float acc[4][4][4];
#pragma unroll
    for (int i = 0; i < 4; ++i)
#pragma unroll
        for (int j = 0; j < 4; ++j)
#pragma unroll
            for (int q = 0; q < 4; ++q) acc[i][j][q] = 0.f;

    const int r0 = tid >> 2;
    const int c0 = (tid & 3) * 8;
    const int nk = K / 32;

    const int aOff = (wm * 64 + (lane & 7) + ((lane >> 3) & 1) * 8) * TW + (lane >> 4) * 8;
    const int lb = lane & 15;
    const int bOff = (wn * 32 + (lb & 7)) * TW + ((lb >> 3) & 1) * 8;

    {
        __nv_bfloat16* s = smx;
#pragma unroll
        for (int p = 0; p < 2; ++p) {
            int row = r0 + p * 64;
            size_t ga = (size_t)(bm + row) * K + c0;
            size_t gw = (size_t)(bn + row) * K + c0;
            int so = row * TW + c0;
            cpa16(s + 0 * PL + so, Ah + ga);
            cpa16(s + 1 * PL + so, Al + ga);
            cpa16(s + 2 * PL + so, Wh + gw);
            cpa16(s + 3 * PL + so, Wl + gw);
        }
        cpa_commit();
    }

    for (int kt = 0; kt < nk; ++kt) {
        cpa_wait0();
        __syncthreads();

        if (kt + 1 < nk) {
            __nv_bfloat16* s = smx + ((kt + 1) & 1) * GBUF;
            int k0 = (kt + 1) * 32;
#pragma unroll
            for (int p = 0; p < 2; ++p) {
                int row = r0 + p * 64;
                size_t ga = (size_t)(bm + row) * K + k0 + c0;
                size_t gw = (size_t)(bn + row) * K + k0 + c0;
                int so = row * TW + c0;
                cpa16(s + 0 * PL + so, Ah + ga);
                cpa16(s + 1 * PL + so, Al + ga);
                cpa16(s + 2 * PL + so, Wh + gw);
                cpa16(s + 3 * PL + so, Wl + gw);
            }
            cpa_commit();
        }

        const __nv_bfloat16* sb = smx + (kt & 1) * GBUF;

#pragma unroll
        for (int ks = 0; ks < 2; ++ks) {
            unsigned aH[4][4], aL[4][4], bH[4][2], bL[4][2];
#pragma unroll
            for (int i = 0; i < 4; ++i) {
                int off = aOff + i * 16 * TW + ks * 16;
                ldsm4(aH[i], sb + 0 * PL + off);
                ldsm4(aL[i], sb + 1 * PL + off);
            }
#pragma unroll
            for (int j = 0; j < 4; ++j) {
                int off = bOff + j * 8 * TW + ks * 16;
                ldsm2(bH[j], sb + 2 * PL + off);
                ldsm2(bL[j], sb + 3 * PL + off);
            }
#pragma unroll
            for (int i = 0; i < 4; ++i)
#pragma unroll
                for (int j = 0; j < 4; ++j) {
                    mma_bf16(acc[i][j], aH[i], bH[j]);
                    mma_bf16(acc[i][j], aH[i], bL[j]);
                    mma_bf16(acc[i][j], aL[i], bH[j]);
                }
        }
    }

#pragma unroll
    for (int i = 0; i < 4; ++i) {
        int row0 = bm + wm * 64 + i * 16 + g;
#pragma unroll
        for (int j = 0; j < 4; ++j) {
            int col = bn + wn * 32 + j * 8 + t * 2;
            float b0 = bias[col], b1 = bias[col + 1];
            float v00 = acc[i][j][0] + b0, v01 = acc[i][j][1] + b1;
            float v10 = acc[i][j][2] + b0, v11 = acc[i][j][3] + b1;
            if (CH) {
                size_t p0 = (size_t)row0 * N + col;
                size_t p1 = (size_t)(row0 + 8) * N + col;
                __nv_bfloat16 h00 = __float2bfloat16(v00), h01 = __float2bfloat16(v01);
                __nv_bfloat16 h10 = __float2bfloat16(v10), h11 = __float2bfloat16(v11);
                *(__nv_bfloat162*)(CH + p0) = __nv_bfloat162(h00, h01);
                *(__nv_bfloat162*)(CH + p1) = __nv_bfloat162(h10, h11);
                *(__nv_bfloat162*)(CL + p0) = __nv_bfloat162(
                    __float2bfloat16(v00 - __bfloat162float(h00)),
                    __float2bfloat16(v01 - __bfloat162float(h01)));
                *(__nv_bfloat162*)(CL + p1) = __nv_bfloat162(
                    __float2bfloat16(v10 - __bfloat162float(h10)),
                    __float2bfloat16(v11 - __bfloat162float(h11)));
            } else {
                *(float2*)(C + (size_t)row0 * N + col) = make_float2(v00, v01);
                *(float2*)(C + (size_t)(row0 + 8) * N + col) = make_float2(v10, v11);
            }
        }
    }
}

// ---------------------------------------------------------------------------
// Persistent tensor-core bidirectional GRU layer: 256 blocks (128/dir),
// 8 units/block, 2 CTAs/SM. W-hi in registers, W-lo in smem.
// ---------------------------------------------------------------------------
constexpr int WSL_U32 = 3 * 64 * 32 * 2;                       // 12288
constexpr int REC_SMEM = WSL_U32 * 4 + (8 * 3 * 32 * 4) * 4;   // 61440

__device__ __forceinline__ unsigned ld_acquire(const unsigned* p) {
    unsigned v;
    asm volatile("ld.global.acquire.gpu.u32 %0, [%1];" : "=r"(v) : "l"(p) : "memory");
    return v;
}
__device__ __forceinline__ void red_release_add(unsigned* p, unsigned v) {
    asm volatile("red.release.gpu.global.add.u32 [%0], %1;" :: "l"(p), "r"(v) : "memory");
}

__global__ void __launch_bounds__(256, 2) gru_layer_tc_kernel(
    const unsigned* __restrict__ WFH, const unsigned* __restrict__ WFL,
    const float* __restrict__ bhh,
    const float* __restrict__ gx,
    __nv_bfloat16* __restrict__ YH, __nv_bfloat16* __restrict__ YL,
    unsigned* __restrict__ HF,
    unsigned* __restrict__ bar)
{
    extern __shared__ unsigned smu[];
    unsigned* wsL = smu;                       // [t3][ks64][lane32][2]
    float* red = (float*)(smu + WSL_U32);      // [w8][t3][lane32][4]

    const int tid  = threadIdx.x;
    const int dir  = blockIdx.x >> 7;
    const int blk  = blockIdx.x & 127;
    const int B16  = blk >> 1;
    const int half = blk & 1;
    const int u0   = blk * 8;
    const int lane = tid & 31, w = tid >> 5;
    unsigned* bard = bar + dir * 32;

    // W-lo fragments -> smem (3 tile chunks, each 4096 u32 contiguous)
    {
        const unsigned* lbase = WFL + (size_t)(dir * 64 + B16) * (6 * 4096);
#pragma unroll
        for (int t = 0; t < 3; ++t) {
            const uint4* src = (const uint4*)(lbase + (t * 2 + half) * 4096);
            uint4* dst = (uint4*)(wsL + t * 4096);
            for (int i = tid; i < 1024; i += 256) dst[i] = src[i];
        }
    }

    // W-hi fragments -> registers (this warp's 8 ksteps x 3 tiles)
    unsigned bHreg[8][3][2];
    {
        const unsigned* hbase = WFH + (size_t)(dir * 64 + B16) * (6 * 4096);
#pragma unroll
        for (int kk = 0; kk < 8; ++kk) {
            int ks = w * 8 + kk;
#pragma unroll
            for (int t = 0; t < 3; ++t) {
                uint2 v = *(const uint2*)(hbase + (t * 2 + half) * 4096 + ks * 64 + lane * 2);
                bHreg[kk][t][0] = v.x;
                bHreg[kk][t][1] = v.y;
            }
        }
    }

    // Gate-thread constants (tid < 128): gb = batch, gu = unit within block
    const bool gactive = tid < 128;
    const int gb = tid >> 3;
    const int gu = tid & 7;
    const int gj = u0 + gu;
    float br = 0.f, bz = 0.f, bn2 = 0.f;
    if (gactive) {
        br  = bhh[dir * 3072 + gj];
        bz  = bhh[dir * 3072 + 1024 + gj];
        bn2 = bhh[dir * 3072 + 2048 + gj];
    }
    float hprev = 0.f;

    const int ksb   = blk >> 1;
    const int wlane = ((gb & 7) << 2) + (gu >> 1);
    const int wreg  = (half ? 2 : 0) + ((gb >= 8) ? 1 : 0);
    const int widx  = (ksb * 32 + wlane) * 4 + wreg;
    const int foff  = wlane * 4 + (gu & 1) + ((gb >= 8) ? 2 : 0);

    // Prefetch gx for s=0
    float xr = 0.f, xz = 0.f, xn = 0.f;
    if (gactive) {
        int tt0 = dir ? (Tt - 1) : 0;
        const float* gxp = gx + (size_t)(tt0 * 16 + gb) * 6144 + dir * 3072;
        xr = __ldg(gxp + gj);
        xz = __ldg(gxp + 1024 + gj);
        xn = __ldg(gxp + 2048 + gj);
    }

    __syncthreads();

    for (int s = 0; s < Tt; ++s) {
        const int cur = s & 1, nxt = cur ^ 1;
        const int tt  = dir ? (Tt - 1 - s) : s;

        float acc[3][4];
#pragma unroll
        for (int t = 0; t < 3; ++t)
#pragma unroll
            for (int q = 0; q < 4; ++q) acc[t][q] = 0.f;

        const unsigned* hfH = HF + ((size_t)(cur * 2 + dir) * 2 + 0) * 8192;
        const unsigned* hfL = HF + ((size_t)(cur * 2 + dir) * 2 + 1) * 8192;

#pragma unroll
        for (int kk = 0; kk < 8; ++kk) {
            int ks = w * 8 + kk;
            uint4 AHv = __ldcg((const uint4*)(hfH + (ks * 32 + lane) * 4));
            uint4 ALv = __ldcg((const uint4*)(hfL + (ks * 32 + lane) * 4));
            unsigned aH[4] = {AHv.x, AHv.y, AHv.z, AHv.w};
            unsigned aL[4] = {ALv.x, ALv.y, ALv.z, ALv.w};
#pragma unroll
            for (int t = 0; t < 3; ++t) {
                uint2 bLv = *(const uint2*)&wsL[t * 4096 + ks * 64 + lane * 2];
                unsigned bL[2] = {bLv.x, bLv.y};
                mma_bf16(acc[t], aH, bHreg[kk][t]);
                mma_bf16(acc[t], aL, bHreg[kk][t]);
                mma_bf16(acc[t], aH, bL);
            }
        }
#pragma unroll
        for (int t = 0; t < 3; ++t)
            *(float4*)&red[((w * 3 + t) * 32 + lane) * 4] =
                make_float4(acc[t][0], acc[t][1], acc[t][2], acc[t][3]);
        __syncthreads();

        if (gactive) {
            float ghr = br, ghz = bz, ghn = bn2;
#pragma unroll
            for (int ww = 0; ww < 8; ++ww) {
                ghr += red[(ww * 3 + 0) * 128 + foff];
                ghz += red[(ww * 3 + 1) * 128 + foff];
                ghn += red[(ww * 3 + 2) * 128 + foff];
            }
            float r = 1.f / (1.f + expf(-(xr + ghr)));
            float z = 1.f / (1.f + expf(-(xz + ghz)));
            float n = tanhf(xn + r * ghn);
            float hnew = (1.f - z) * n + z * hprev;
            hprev = hnew;

            __nv_bfloat16 hhi = __float2bfloat16(hnew);
            float rlo = hnew - __bfloat162float(hhi);
            __nv_bfloat16 hlo = __float2bfloat16(rlo);
            unsigned vh = (unsigned)__bfloat16_as_ushort(hhi);
            unsigned vl = (unsigned)__bfloat16_as_ushort(hlo);
            unsigned ph = __shfl_down_sync(0xffffffffu, vh, 1);
            unsigned pl = __shfl_down_sync(0xffffffffu, vl, 1);
            if ((gu & 1) == 0) {
                unsigned hp = (ph << 16) | vh;
                unsigned lp = (pl << 16) | vl;
                unsigned* oH = HF + ((size_t)(nxt * 2 + dir) * 2 + 0) * 8192;
                unsigned* oL = HF + ((size_t)(nxt * 2 + dir) * 2 + 1) * 8192;
                oH[widx] = hp;
                oL[widx] = lp;
                size_t yi = (size_t)(tt * 16 + gb) * 1024 + dir * 512 + (gj >> 1);
                ((unsigned*)YH)[yi] = hp;
                ((unsigned*)YL)[yi] = lp;
            }

            // Prefetch gx for next step (independent of barrier)
            if (s + 1 < Tt) {
                int ttn = dir ? (Tt - 2 - s) : (s + 1);
                const float* gxn = gx + (size_t)(ttn * 16 + gb) * 6144 + dir * 3072;
                xr = __ldg(gxn + gj);
                xz = __ldg(gxn + 1024 + gj);
                xn = __ldg(gxn + 2048 + gj);
            }
        }

        __syncthreads();
        if (tid == 0) {
            red_release_add(bard, 1u);
            unsigned tgt = (unsigned)(s + 1) * 128;
            while (ld_acquire(bard) < tgt) { }
        }
        __syncthreads();
    }
}

// ---------------------------------------------------------------------------
extern "C" void kernel_launch(void* const* d_in, const int* in_sizes, int n_in,
                              void* d_out, int out_size)
{
    const float* inp     = (const float*)d_in[0];
    const float* w_in    = (const float*)d_in[1];
    const float* b_in    = (const float*)d_in[2];
    const float* w_ih_l0 = (const float*)d_in[3];
    const float* w_hh_l0 = (const float*)d_in[4];
    const float* b_ih_l0 = (const float*)d_in[5];
    const float* b_hh_l0 = (const float*)d_in[6];
    const float* w_ih_l1 = (const float*)d_in[7];
    const float* w_hh_l1 = (const float*)d_in[8];
    const float* b_ih_l1 = (const float*)d_in[9];
    const float* b_hh_l1 = (const float*)d_in[10];
    const float* w_out   = (const float*)d_in[11];
    const float* b_out   = (const float*)d_in[12];
    float* out = (float*)d_out;

    float* S = nullptr;
    cudaGetSymbolAddress((void**)&S, g_scratch);
    __nv_bfloat16* BF = nullptr;
    cudaGetSymbolAddress((void**)&BF, g_bf);

    float* GX0  = S + OFF_GX0;
    float* GX1  = S + OFF_GX1;
    float* OUTT = S + OFF_OUTT;
    unsigned* WFH0 = (unsigned*)(S + OFF_WFH0);
    unsigned* WFL0 = (unsigned*)(S + OFF_WFL0);
    unsigned* WFH1 = (unsigned*)(S + OFF_WFH1);
    unsigned* WFL1 = (unsigned*)(S + OFF_WFL1);
    unsigned* HF0  = (unsigned*)(S + OFF_HF0);
    unsigned* HF1  = (unsigned*)(S + OFF_HF1);
    unsigned* BAR0 = (unsigned*)(S + OFF_BAR0);
    unsigned* BAR1 = (unsigned*)(S + OFF_BAR1);

    cudaFuncSetAttribute(gemm_bf16_split_kernel,
                         cudaFuncAttributeMaxDynamicSharedMemorySize, SMEM_GEMM);
    cudaFuncSetAttribute(gru_layer_tc_kernel,
                         cudaFuncAttributeMaxDynamicSharedMemorySize, REC_SMEM);

    const int M = Tt * Bb;  // 8192

    // 1) Mega-prep
    prep_kernel<<<NB_PREP, 256>>>(inp, w_in, w_ih_l0, w_ih_l1, w_out,
                                  w_hh_l0, w_hh_l1, BF,
                                  WFH0, WFL0, WFH1, WFL1, HF0, HF1, BAR0, BAR1);

    // 2) Input projection
    gemm_bf16_split_kernel<<<dim3(F / 128, M / 128), 256, SMEM_GEMM>>>(
        BF + BOFF_XH, BF + BOFF_XL, BF + BOFF_WINH, BF + BOFF_WINL, b_in,
        nullptr, BF + BOFF_H0H, BF + BOFF_H0L, M, F, INP);

    // 3) Layer 0 gx
    gemm_bf16_split_kernel<<<dim3(6 * F / 128, M / 128), 256, SMEM_GEMM>>>(
        BF + BOFF_H0H, BF + BOFF_H0L, BF + BOFF_WI0H, BF + BOFF_WI0L, b_ih_l0,
        GX0, nullptr, nullptr, M, 6 * F, F);

    // 4) Layer 0 recurrence  <-- ncu capture slot
    gru_layer_tc_kernel<<<256, 256, REC_SMEM>>>(
        WFH0, WFL0, b_hh_l0, GX0, BF + BOFF_Y0H, BF + BOFF_Y0L, HF0, BAR0);

    // 5) Layer 1 gx
    gemm_bf16_split_kernel<<<dim3(6 * F / 128, M / 128), 256, SMEM_GEMM>>>(
        BF + BOFF_Y0H, BF + BOFF_Y0L, BF + BOFF_WI1H, BF + BOFF_WI1L, b_ih_l1,
        GX1, nullptr, nullptr, M, 6 * F, 2 * F);

    // 6) Layer 1 recurrence
    gru_layer_tc_kernel<<<256, 256, REC_SMEM>>>(
        WFH1, WFL1, b_hh_l1, GX1, BF + BOFF_Y1H, BF + BOFF_Y1L, HF1, BAR1);

    // 7) Output projection
    gemm_bf16_split_kernel<<<dim3(OUTD / 128, M / 128), 256, SMEM_GEMM>>>(
        BF + BOFF_Y1H, BF + BOFF_Y1L, BF + BOFF_WOH, BF + BOFF_WOL, b_out,
        OUTT, nullptr, nullptr, M, OUTD, 2 * F);

    // 8) Final transpose
    transpose_out_kernel<<<dim3(Tt / 32, OUTD / 32, Bb), dim3(32, 8)>>>(OUTT, out);
}